// round 13
// baseline (speedup 1.0000x reference)
#include <cuda_runtime.h>
#include <cuda_bf16.h>
#include <math.h>

#define Nn 20000
#define Ee 256000
#define NODE_DIM 128
#define EDGE_DIM 8
#define HID 64
#define HEADS 4
#define HC 256
#define LAYERS 3
#define CLASSES 3
#define GRAPHS 64
#define SCAN_CHUNK 1024
#define SCAN_BLOCKS ((Nn + SCAN_CHUNK - 1) / SCAN_CHUNK)

// ---------------- scratch (static device allocations; no cudaMalloc) -------
__device__ float d_h0[Nn * HID];
__device__ float d_h1[Nn * HID];
__device__ float d_qf[Nn * HC];
__device__ float d_qef[Nn * HC];
__device__ __nv_bfloat16 d_kvb[Nn * 512];         // interleaved [k(256) | v(256)]
__device__ __nv_bfloat16 d_eb[Ee * HID];
__device__ __nv_bfloat16 d_ebp[Ee * HID];         // eb permuted to CSR order
__device__ __nv_bfloat16 d_t[Nn * HC];            // bf16 attention outputs
__device__ __nv_bfloat16 d_amean[Nn * HID];
__device__ float d_Bp[LAYERS * HID * 1024];
__device__ float d_biasp[LAYERS * 1024];
__device__ float d_Bc[LAYERS * 320 * HID];
__device__ unsigned d_BfQ[LAYERS * HID * 1024];   // tf32 frag-order qkvqe B
__device__ unsigned d_BfC[LAYERS * 320 * HID];    // tf32 frag-order conv B
__device__ unsigned d_BfH[NODE_DIM * HID];        // tf32 frag-order node_W
__device__ unsigned d_BfE[HID * HID];             // tf32 frag-order e2_W
__device__ int d_cnt[Nn];
__device__ int d_off[Nn + 1];
__device__ int d_cur[Nn];
__device__ int d_partial[SCAN_BLOCKS];
__device__ int d_base[SCAN_BLOCKS];
__device__ int d_srcs[Ee];
__device__ int d_eids[Ee];

// ---------------- tf32 / mma helpers ---------------------------------------
__device__ __forceinline__ unsigned f2tf(float f) {
    unsigned u;
    asm("cvt.rna.tf32.f32 %0, %1;" : "=r"(u) : "f"(f));
    return u;
}

__device__ __forceinline__ void mma8(float c[4], unsigned a0, unsigned a1, unsigned a2,
                                     unsigned a3, unsigned b0, unsigned b1) {
    asm volatile(
        "mma.sync.aligned.m16n8k8.row.col.f32.tf32.tf32.f32 "
        "{%0,%1,%2,%3}, {%4,%5,%6,%7}, {%8,%9}, {%0,%1,%2,%3};"
        : "+f"(c[0]), "+f"(c[1]), "+f"(c[2]), "+f"(c[3])
        : "r"(a0), "r"(a1), "r"(a2), "r"(a3), "r"(b0), "r"(b1));
}

// stage 128x32 fp32 -> tf32 smem tile (pad 36 => conflict-free frag LDS)
__device__ __forceinline__ void stage_A(const float* __restrict__ A, int lda, int bm, int M,
                                        int k0, unsigned (*As)[36], int tid) {
    int ar = tid >> 1, ac = (tid & 1) * 16;
    int row = bm + ar;
    const float* Ap = A + (size_t)row * lda + k0 + ac;
    bool ok = row < M;
#pragma unroll
    for (int j = 0; j < 4; j++) {
        float4 v = ok ? *(const float4*)(Ap + 4 * j) : make_float4(0.f, 0.f, 0.f, 0.f);
        As[ar][ac + 4 * j + 0] = f2tf(v.x);
        As[ar][ac + 4 * j + 1] = f2tf(v.y);
        As[ar][ac + 4 * j + 2] = f2tf(v.z);
        As[ar][ac + 4 * j + 3] = f2tf(v.w);
    }
}

// stage 128x32 bf16 -> tf32 smem tile
__device__ __forceinline__ void stage_Abf(const __nv_bfloat16* __restrict__ A, int lda, int bm,
                                          int M, int k0, unsigned (*As)[36], int tid) {
    int ar = tid >> 1, ac = (tid & 1) * 16;
    int row = bm + ar;
    const __nv_bfloat16* Ap = A + (size_t)row * lda + k0 + ac;
    bool ok = row < M;
    uint4 z = make_uint4(0, 0, 0, 0);
    uint4 r0 = ok ? *(const uint4*)Ap : z;
    uint4 r1 = ok ? *(const uint4*)(Ap + 8) : z;
    const __nv_bfloat162* p0 = (const __nv_bfloat162*)&r0;
    const __nv_bfloat162* p1 = (const __nv_bfloat162*)&r1;
#pragma unroll
    for (int j = 0; j < 4; j++) {
        float2 f0 = __bfloat1622float2(p0[j]);
        float2 f1 = __bfloat1622float2(p1[j]);
        As[ar][ac + 2 * j + 0] = f2tf(f0.x);
        As[ar][ac + 2 * j + 1] = f2tf(f0.y);
        As[ar][ac + 8 + 2 * j + 0] = f2tf(f1.x);
        As[ar][ac + 8 + 2 * j + 1] = f2tf(f1.y);
    }
}

// one 32-wide K chunk: 4 k-steps of m16n8k8 across warp's 32x32 tile
__device__ __forceinline__ void mma_stage(const unsigned (*As)[36], const uint2* __restrict__ bst,
                                          float acc[2][4][4], int wm, int wn, int g, int tg,
                                          int lane) {
#pragma unroll
    for (int s = 0; s < 4; s++) {
        unsigned a[2][4];
#pragma unroll
        for (int t = 0; t < 2; t++) {
            int r = wm * 32 + t * 16 + g;
            a[t][0] = As[r][s * 8 + tg];
            a[t][1] = As[r + 8][s * 8 + tg];
            a[t][2] = As[r][s * 8 + tg + 4];
            a[t][3] = As[r + 8][s * 8 + tg + 4];
        }
        const uint2* bp = bst + ((s * 2 + wn) * 4) * 32 + lane;
#pragma unroll
        for (int u = 0; u < 4; u++) {
            uint2 b = bp[u * 32];
#pragma unroll
            for (int t = 0; t < 2; t++)
                mma8(acc[t][u], a[t][0], a[t][1], a[t][2], a[t][3], b.x, b.y);
        }
    }
}

// ---------------- CSR build -------------------------------------------------
__global__ void zero_int_kernel(int* p, int n) {
    int i = blockIdx.x * blockDim.x + threadIdx.x;
    if (i < n) p[i] = 0;
}

__global__ void count_kernel(const int* __restrict__ edge_index, int* __restrict__ cnt) {
    int i = blockIdx.x * blockDim.x + threadIdx.x;
    if (i < Ee) atomicAdd(&cnt[edge_index[Ee + i]], 1);
}

__global__ void scan_partial_kernel(const int* __restrict__ cnt, int* __restrict__ partial) {
    __shared__ int sh[256];
    int b = blockIdx.x, tid = threadIdx.x;
    int base = b * SCAN_CHUNK;
    int s = 0;
#pragma unroll
    for (int j = 0; j < SCAN_CHUNK / 256; j++) {
        int i = base + j * 256 + tid;
        s += (i < Nn) ? cnt[i] : 0;
    }
    sh[tid] = s;
    __syncthreads();
    for (int st = 128; st >= 1; st >>= 1) {
        if (tid < st) sh[tid] += sh[tid + st];
        __syncthreads();
    }
    if (tid == 0) partial[b] = sh[0];
}

__global__ void scan_base_kernel(const int* __restrict__ partial, int* __restrict__ base,
                                 int* __restrict__ off) {
    if (threadIdx.x == 0) {
        int run = 0;
        for (int i = 0; i < SCAN_BLOCKS; i++) { base[i] = run; run += partial[i]; }
        off[Nn] = run;
    }
}

__global__ void scan_final_kernel(const int* __restrict__ cnt, const int* __restrict__ base,
                                  int* __restrict__ off, int* __restrict__ cur) {
    __shared__ int sh[SCAN_CHUNK];
    int b = blockIdx.x, tid = threadIdx.x;
    int i = b * SCAN_CHUNK + tid;
    int v = (i < Nn) ? cnt[i] : 0;
    sh[tid] = v;
    __syncthreads();
    for (int s = 1; s < SCAN_CHUNK; s <<= 1) {
        int t2 = (tid >= s) ? sh[tid - s] : 0;
        __syncthreads();
        sh[tid] += t2;
        __syncthreads();
    }
    if (i < Nn) {
        int excl = sh[tid] - v + base[b];
        off[i] = excl;
        cur[i] = excl;
    }
}

__global__ void scatter_kernel(const int* __restrict__ edge_index, int* __restrict__ cur,
                               int* __restrict__ srcs, int* __restrict__ eids) {
    int i = blockIdx.x * blockDim.x + threadIdx.x;
    if (i < Ee) {
        int src = edge_index[i];
        int dst = edge_index[Ee + i];
        int pos = atomicAdd(&cur[dst], 1);
        srcs[pos] = src;
        eids[pos] = i;
    }
}

// permute eb into CSR order: ebp[i] = eb[eids[i]]
__global__ void reorder_e_kernel(const __nv_bfloat16* __restrict__ eb,
                                 const int* __restrict__ eids,
                                 __nv_bfloat16* __restrict__ ebp) {
    int idx = blockIdx.x * blockDim.x + threadIdx.x;
    if (idx >= Ee * 8) return;
    int i = idx >> 3;
    int c = (idx & 7) * 8;
    int eid = eids[i];
    *(uint4*)(ebp + (size_t)i * 64 + c) = *(const uint4*)(eb + (size_t)eid * 64 + c);
}

// ---------------- weight packing (fused) -------------------------------------
__global__ void pack_stage1(const float* __restrict__ Wq, const float* __restrict__ bq,
                            const float* __restrict__ Wk, const float* __restrict__ bk,
                            const float* __restrict__ Wv, const float* __restrict__ bv,
                            const float* __restrict__ We, const float* __restrict__ Wskip,
                            float* __restrict__ Bp, float* __restrict__ biasp,
                            float* __restrict__ Bc) {
    int idx = blockIdx.x * blockDim.x + threadIdx.x;
    if (idx < LAYERS * 65536) {
        int l = idx >> 16;
        int rem = idx & 65535;
        int j = rem >> 10;
        int col = rem & 1023;
        const float* Wql = Wq + l * 16384;
        const float* Wkl = Wk + l * 16384;
        const float* Wvl = Wv + l * 16384;
        const float* Wel = We + l * 16384;
        float v;
        if (col < 256) v = Wql[j * 256 + col];
        else if (col < 512) v = Wkl[j * 256 + col - 256];
        else if (col < 768) v = Wvl[j * 256 + col - 512];
        else {
            int d2 = col - 768; int h = d2 >> 6; int d = d2 & 63;
            float s = 0.f;
            for (int c = 0; c < 64; c++)
                s += Wql[j * 256 + h * 64 + c] * Wel[d * 256 + h * 64 + c];
            v = s;
        }
        Bp[idx] = v;
        if (j == 0) {
            float bvv;
            if (col < 256) bvv = bq[l * 256 + col];
            else if (col < 512) bvv = bk[l * 256 + col - 256];
            else if (col < 768) bvv = bv[l * 256 + col - 512];
            else {
                int d2 = col - 768; int h = d2 >> 6; int d = d2 & 63;
                float s = 0.f;
                for (int c = 0; c < 64; c++)
                    s += bq[l * 256 + h * 64 + c] * Wel[d * 256 + h * 64 + c];
                bvv = s;
            }
            biasp[l * 1024 + col] = bvv;
        }
    } else {
        int j = idx - LAYERS * 65536;
        if (j >= LAYERS * 320 * 64) return;
        int l = j / (320 * 64);
        int r = (j >> 6) % 320;
        int c = j & 63;
        float v;
        if (r < 256) {
            int h = r >> 6, d = r & 63;
            v = We[l * 16384 + d * 256 + h * 64 + c];
        } else {
            v = Wskip[l * 4096 + (r - 256) * 64 + c];
        }
        Bc[j] = v;
    }
}

__device__ __forceinline__ void frag_pack(const float* __restrict__ B, unsigned* __restrict__ out,
                                          int idx, int K, int Ncols) {
    int ks_total = K >> 3;
    int p = idx & 1;
    int lane = (idx >> 1) & 31;
    int u = (idx >> 6) & 3;
    int wn = (idx >> 8) & 1;
    int rest = idx >> 9;
    int ks = rest % ks_total;
    int bnb = rest / ks_total;
    int k = ks * 8 + (lane & 3) + 4 * p;
    int n = bnb * 64 + wn * 32 + u * 8 + (lane >> 2);
    out[idx] = f2tf(B[k * Ncols + n]);
}

__global__ void pack_frag(const float* __restrict__ B, unsigned* __restrict__ out,
                          int K, int Ncols) {
    int idx = blockIdx.x * blockDim.x + threadIdx.x;
    if (idx < K * Ncols) frag_pack(B, out, idx, K, Ncols);
}

__global__ void pack_stage2(const float* __restrict__ Bp, const float* __restrict__ Bc,
                            unsigned* __restrict__ BfQ, unsigned* __restrict__ BfC) {
    int idx = blockIdx.x * blockDim.x + threadIdx.x;
    if (idx < LAYERS * 65536) {
        int l = idx >> 16;
        frag_pack(Bp + l * 65536, BfQ + l * 65536, idx & 65535, 64, 1024);
    } else {
        int j = idx - LAYERS * 65536;
        if (j >= LAYERS * 20480) return;
        int l = j / 20480;
        frag_pack(Bc + l * 20480, BfC + l * 20480, j % 20480, 320, 64);
    }
}

// ---------------- node projection (tf32 MMA, double-buffered) ---------------
__global__ void gemm_h_mma(const float* __restrict__ A, const unsigned* __restrict__ Bf,
                           const float* __restrict__ bias, float* __restrict__ C,
                           int M, int K, int lda) {
    __shared__ unsigned As[2][128][36];
    float acc[2][4][4] = {};
    int bm = blockIdx.x * 128;
    int tid = threadIdx.x, w = tid >> 5, lane = tid & 31;
    int wm = w & 3, wn = w >> 2, g = lane >> 2, tg = lane & 3;
    int nst = K >> 5;
    stage_A(A, lda, bm, M, 0, As[0], tid);
    __syncthreads();
    for (int st = 0; st < nst; st++) {
        int cb = st & 1;
        if (st + 1 < nst) stage_A(A, lda, bm, M, (st + 1) * 32, As[cb ^ 1], tid);
        mma_stage(As[cb], (const uint2*)Bf + st * 1024, acc, wm, wn, g, tg, lane);
        __syncthreads();
    }
#pragma unroll
    for (int u = 0; u < 4; u++) {
        int col = wn * 32 + u * 8 + 2 * tg;
        float2 bb = *(const float2*)(bias + col);
#pragma unroll
        for (int t = 0; t < 2; t++) {
            int row = bm + wm * 32 + t * 16 + g;
            if (row < M) {
                float2 o = {acc[t][u][0] + bb.x, acc[t][u][1] + bb.y};
                *(float2*)(C + (size_t)row * 64 + col) = o;
            }
            if (row + 8 < M) {
                float2 o = {acc[t][u][2] + bb.x, acc[t][u][3] + bb.y};
                *(float2*)(C + (size_t)(row + 8) * 64 + col) = o;
            }
        }
    }
}

// ---------------- fused QKVQE (tf32 MMA): A staged once per 2 n-blocks ------
__global__ void __launch_bounds__(256)
gemm_qkvqe_mma(const float* __restrict__ h, const unsigned* __restrict__ BfQ,
               const float* __restrict__ biasp,
               float* __restrict__ qf, float* __restrict__ qef,
               __nv_bfloat16* __restrict__ kvb) {
    __shared__ unsigned As[2][128][36];
    int bm = blockIdx.x * 128;
    int tid = threadIdx.x, w = tid >> 5, lane = tid & 31;
    int wm = w & 3, wn = w >> 2, g = lane >> 2, tg = lane & 3;
    stage_A(h, 64, bm, Nn, 0, As[0], tid);
    stage_A(h, 64, bm, Nn, 32, As[1], tid);
    __syncthreads();
    for (int j = 0; j < 2; j++) {
        int bn = blockIdx.y * 2 + j;
        const uint2* Bfb = (const uint2*)BfQ + bn * 2048;
        float acc[2][4][4] = {};
        mma_stage(As[0], Bfb, acc, wm, wn, g, tg, lane);
        mma_stage(As[1], Bfb + 1024, acc, wm, wn, g, tg, lane);
        int sec = bn >> 2;
#pragma unroll
        for (int u = 0; u < 4; u++) {
            int colL = wn * 32 + u * 8 + 2 * tg;
            float2 bb = *(const float2*)(biasp + bn * 64 + colL);
            int coff = (bn & 3) * 64 + colL;
#pragma unroll
            for (int t = 0; t < 2; t++) {
#pragma unroll
                for (int hh = 0; hh < 2; hh++) {
                    int row = bm + wm * 32 + t * 16 + g + 8 * hh;
                    if (row >= Nn) continue;
                    float v0 = acc[t][u][2 * hh + 0] + bb.x;
                    float v1 = acc[t][u][2 * hh + 1] + bb.y;
                    if (sec == 0) {
                        float2 o = {v0, v1};
                        *(float2*)(qf + (size_t)row * 256 + coff) = o;
                    } else if (sec == 3) {
                        float2 o = {v0, v1};
                        *(float2*)(qef + (size_t)row * 256 + coff) = o;
                    } else {
                        __nv_bfloat16* dst = kvb + (size_t)row * 512 + (sec == 2 ? 256 : 0) + coff;
                        *(__nv_bfloat162*)dst = __floats2bfloat162_rn(v0, v1);
                    }
                }
            }
        }
    }
}

// ---------------- fused conv (tf32 MMA, double-buffered) + LN + relu --------
__global__ void conv_ln_mma(const __nv_bfloat16* __restrict__ t, const float* __restrict__ hres,
                            const unsigned* __restrict__ BfC, const float* __restrict__ bskip,
                            const __nv_bfloat16* __restrict__ amean,
                            const float* __restrict__ gam,
                            const float* __restrict__ bet, float* __restrict__ hout) {
    __shared__ unsigned As[2][128][36];
    __shared__ float Ssum[128][2];
    __shared__ float Ssq[128][2];
    float acc[2][4][4] = {};
    int bm = blockIdx.x * 128;
    int tid = threadIdx.x, w = tid >> 5, lane = tid & 31;
    int wm = w & 3, wn = w >> 2, g = lane >> 2, tg = lane & 3;
    stage_Abf(t, 256, bm, Nn, 0, As[0], tid);
    __syncthreads();
    for (int st = 0; st < 10; st++) {
        int cb = st & 1;
        int nx = st + 1;
        if (nx < 8) stage_Abf(t, 256, bm, Nn, nx * 32, As[cb ^ 1], tid);
        else if (nx < 10) stage_A(hres, 64, bm, Nn, (nx - 8) * 32, As[cb ^ 1], tid);
        mma_stage(As[cb], (const uint2*)BfC + st * 1024, acc, wm, wn, g, tg, lane);
        __syncthreads();
    }
    float xs[2][4][4];
#pragma unroll
    for (int u = 0; u < 4; u++) {
        int col = wn * 32 + u * 8 + 2 * tg;
        float2 bb = *(const float2*)(bskip + col);
#pragma unroll
        for (int t2 = 0; t2 < 2; t2++) {
#pragma unroll
            for (int hh = 0; hh < 2; hh++) {
                int row = bm + wm * 32 + t2 * 16 + g + 8 * hh;
                float2 am = make_float2(0.f, 0.f), hr = make_float2(0.f, 0.f);
                if (row < Nn) {
                    am = __bfloat1622float2(
                        *(const __nv_bfloat162*)(amean + (size_t)row * 64 + col));
                    hr = *(const float2*)(hres + (size_t)row * 64 + col);
                }
                xs[t2][u][2 * hh + 0] = acc[t2][u][2 * hh + 0] + bb.x + am.x + hr.x;
                xs[t2][u][2 * hh + 1] = acc[t2][u][2 * hh + 1] + bb.y + am.y + hr.y;
            }
        }
    }
#pragma unroll
    for (int t2 = 0; t2 < 2; t2++) {
#pragma unroll
        for (int hh = 0; hh < 2; hh++) {
            float s = 0.f, q = 0.f;
#pragma unroll
            for (int u = 0; u < 4; u++) {
                float a = xs[t2][u][2 * hh + 0], b = xs[t2][u][2 * hh + 1];
                s += a + b;
                q += a * a + b * b;
            }
            s += __shfl_xor_sync(0xffffffffu, s, 1);
            s += __shfl_xor_sync(0xffffffffu, s, 2);
            q += __shfl_xor_sync(0xffffffffu, q, 1);
            q += __shfl_xor_sync(0xffffffffu, q, 2);
            if (tg == 0) {
                int lr = wm * 32 + t2 * 16 + g + 8 * hh;
                Ssum[lr][wn] = s;
                Ssq[lr][wn] = q;
            }
        }
    }
    __syncthreads();
#pragma unroll
    for (int t2 = 0; t2 < 2; t2++) {
#pragma unroll
        for (int hh = 0; hh < 2; hh++) {
            int lr = wm * 32 + t2 * 16 + g + 8 * hh;
            int row = bm + lr;
            float m = (Ssum[lr][0] + Ssum[lr][1]) * (1.f / 64.f);
            float var = (Ssq[lr][0] + Ssq[lr][1]) * (1.f / 64.f) - m * m;
            float rs = rsqrtf(var + 1e-5f);
            if (row >= Nn) continue;
#pragma unroll
            for (int u = 0; u < 4; u++) {
                int col = wn * 32 + u * 8 + 2 * tg;
                float2 gg = *(const float2*)(gam + col);
                float2 b2 = *(const float2*)(bet + col);
                float2 o;
                o.x = fmaxf((xs[t2][u][2 * hh + 0] - m) * rs * gg.x + b2.x, 0.f);
                o.y = fmaxf((xs[t2][u][2 * hh + 1] - m) * rs * gg.y + b2.y, 0.f);
                *(float2*)(hout + (size_t)row * 64 + col) = o;
            }
        }
    }
}

// ---------------- fused edge MLP (tf32 MMA): eb = bf16(relu(ea@W1+b1)@W2+b2)
__global__ void edge_mlp_mma(const float* __restrict__ ea, const float* __restrict__ W1,
                             const float* __restrict__ b1, const unsigned* __restrict__ BfE,
                             const float* __restrict__ b2, __nv_bfloat16* __restrict__ eb) {
    __shared__ unsigned As[128][68];
    __shared__ float W1s[EDGE_DIM * HID];
    __shared__ float b1s[HID];
    int tid = threadIdx.x, w = tid >> 5, lane = tid & 31;
    int wm = w & 3, wn = w >> 2, g = lane >> 2, tg = lane & 3;
    int be = blockIdx.x * 128;
    for (int i = tid; i < EDGE_DIM * HID; i += 256) W1s[i] = W1[i];
    if (tid < HID) b1s[tid] = b1[tid];
    __syncthreads();
    {
        int r = tid >> 1, half = tid & 1;
        float av[EDGE_DIM];
        const float* eap = ea + (size_t)(be + r) * EDGE_DIM;
#pragma unroll
        for (int d = 0; d < EDGE_DIM; d++) av[d] = eap[d];
#pragma unroll
        for (int c = 0; c < 32; c++) {
            int col = half * 32 + c;
            float s = b1s[col];
#pragma unroll
            for (int d = 0; d < EDGE_DIM; d++) s += av[d] * W1s[d * HID + col];
            As[r][col] = f2tf(fmaxf(s, 0.f));
        }
    }
    __syncthreads();
    float acc[2][4][4] = {};
#pragma unroll
    for (int st = 0; st < 2; st++) {
#pragma unroll
        for (int s = 0; s < 4; s++) {
            unsigned a[2][4];
#pragma unroll
            for (int t = 0; t < 2; t++) {
                int r = wm * 32 + t * 16 + g;
                a[t][0] = As[r][st * 32 + s * 8 + tg];
                a[t][1] = As[r + 8][st * 32 + s * 8 + tg];
                a[t][2] = As[r][st * 32 + s * 8 + tg + 4];
                a[t][3] = As[r + 8][st * 32 + s * 8 + tg + 4];
            }
            const uint2* bp = (const uint2*)BfE + st * 1024 + ((s * 2 + wn) * 4) * 32 + lane;
#pragma unroll
            for (int u = 0; u < 4; u++) {
                uint2 b = bp[u * 32];
#pragma unroll
                for (int t = 0; t < 2; t++)
                    mma8(acc[t][u], a[t][0], a[t][1], a[t][2], a[t][3], b.x, b.y);
            }
        }
    }
#pragma unroll
    for (int u = 0; u < 4; u++) {
        int col = wn * 32 + u * 8 + 2 * tg;
        float2 bb = *(const float2*)(b2 + col);
#pragma unroll
        for (int t = 0; t < 2; t++) {
#pragma unroll
            for (int hh = 0; hh < 2; hh++) {
                int row = be + wm * 32 + t * 16 + g + 8 * hh;
                float v0 = acc[t][u][2 * hh + 0] + bb.x;
                float v1 = acc[t][u][2 * hh + 1] + bb.y;
                *(__nv_bfloat162*)(eb + (size_t)row * HID + col) = __floats2bfloat162_rn(v0, v1);
            }
        }
    }
}

// ---------------- per-node attention: prefetched gathers ---------------------
__device__ __forceinline__ float dotqk(const float* qv, const float* qev, uint4 kr, uint4 er) {
    const __nv_bfloat162* kp = (const __nv_bfloat162*)&kr;
    const __nv_bfloat162* ep = (const __nv_bfloat162*)&er;
    float p = 0.f;
#pragma unroll
    for (int t = 0; t < 4; t++) {
        float2 kf = __bfloat1622float2(kp[t]);
        float2 ef = __bfloat1622float2(ep[t]);
        p += qv[2 * t] * kf.x + qv[2 * t + 1] * kf.y;
        p += qev[2 * t] * ef.x + qev[2 * t + 1] * ef.y;
    }
    return p;
}

__device__ __forceinline__ void aggr(float* acc, float* tac, float wgt, uint4 vr, uint4 er) {
    const __nv_bfloat162* vp = (const __nv_bfloat162*)&vr;
    const __nv_bfloat162* ep = (const __nv_bfloat162*)&er;
#pragma unroll
    for (int t = 0; t < 4; t++) {
        float2 vf = __bfloat1622float2(vp[t]);
        float2 ef = __bfloat1622float2(ep[t]);
        acc[2 * t + 0] += wgt * vf.x;
        acc[2 * t + 1] += wgt * vf.y;
        tac[2 * t + 0] += wgt * ef.x;
        tac[2 * t + 1] += wgt * ef.y;
    }
}

__global__ void __launch_bounds__(256, 4)
attn_kernel(const float* __restrict__ qf, const float* __restrict__ qef,
            const __nv_bfloat16* __restrict__ kvb, const __nv_bfloat16* __restrict__ ebp,
            const int* __restrict__ off, const int* __restrict__ srcs,
            __nv_bfloat16* __restrict__ t_out, __nv_bfloat16* __restrict__ amean) {
    int warp = (blockIdx.x * blockDim.x + threadIdx.x) >> 5;
    if (warp >= Nn) return;
    int lane = threadIdx.x & 31;
    int g = lane >> 3;
    int li = lane & 7;
    int n = warp;
    int base = n * HC + g * 64 + li * 8;
    int hoff = g * 64 + li * 8;
    float qv[8], qev[8];
    {
        // fold softmax scale (1/8, exact power of 2) into q registers
        float4 a = *(const float4*)(qf + base);
        float4 b = *(const float4*)(qf + base + 4);
        qv[0]=a.x*0.125f; qv[1]=a.y*0.125f; qv[2]=a.z*0.125f; qv[3]=a.w*0.125f;
        qv[4]=b.x*0.125f; qv[5]=b.y*0.125f; qv[6]=b.z*0.125f; qv[7]=b.w*0.125f;
        float4 c = *(const float4*)(qef + base);
        float4 d = *(const float4*)(qef + base + 4);
        qev[0]=c.x*0.125f; qev[1]=c.y*0.125f; qev[2]=c.z*0.125f; qev[3]=c.w*0.125f;
        qev[4]=d.x*0.125f; qev[5]=d.y*0.125f; qev[6]=d.z*0.125f; qev[7]=d.w*0.125f;
    }

    int s0 = off[n], s1 = off[n + 1];
    float denom = 0.f;
    float acc[8] = {}, tac[8] = {};

    // initial L1 prefetch for the first 2 edges
    if (s0 < s1) {
        const char* p0 = (const char*)(kvb + (size_t)srcs[s0] * 512 + hoff);
        asm volatile("prefetch.global.L1 [%0];" :: "l"(p0));
        asm volatile("prefetch.global.L1 [%0+512];" :: "l"(p0));
        if (s0 + 1 < s1) {
            const char* p1 = (const char*)(kvb + (size_t)srcs[s0 + 1] * 512 + hoff);
            asm volatile("prefetch.global.L1 [%0];" :: "l"(p1));
            asm volatile("prefetch.global.L1 [%0+512];" :: "l"(p1));
        }
    }

    int i = s0;
    for (; i + 2 <= s1; i += 2) {
        // prefetch next pair's k/v lines into L1 (no reg/SB cost)
        if (i + 4 <= s1) {
            const char* pf0 = (const char*)(kvb + (size_t)srcs[i + 2] * 512 + hoff);
            const char* pf1 = (const char*)(kvb + (size_t)srcs[i + 3] * 512 + hoff);
            asm volatile("prefetch.global.L1 [%0];" :: "l"(pf0));
            asm volatile("prefetch.global.L1 [%0+512];" :: "l"(pf0));
            asm volatile("prefetch.global.L1 [%0];" :: "l"(pf1));
            asm volatile("prefetch.global.L1 [%0+512];" :: "l"(pf1));
        }
        int n0 = srcs[i];
        int n1 = srcs[i + 1];
        uint4 k0 = *(const uint4*)(kvb + (size_t)n0 * 512 + hoff);
        uint4 k1 = *(const uint4*)(kvb + (size_t)n1 * 512 + hoff);
        uint4 v0 = *(const uint4*)(kvb + (size_t)n0 * 512 + 256 + hoff);
        uint4 v1 = *(const uint4*)(kvb + (size_t)n1 * 512 + 256 + hoff);
        uint4 e0 = *(const uint4*)(ebp + (size_t)i * 64 + li * 8);
        uint4 e1 = *(const uint4*)(ebp + (size_t)(i + 1) * 64 + li * 8);
        float p0 = dotqk(qv, qev, k0, e0);
        float p1 = dotqk(qv, qev, k1, e1);
        p0 += __shfl_xor_sync(0xffffffffu, p0, 1);
        p1 += __shfl_xor_sync(0xffffffffu, p1, 1);
        p0 += __shfl_xor_sync(0xffffffffu, p0, 2);
        p1 += __shfl_xor_sync(0xffffffffu, p1, 2);
        p0 += __shfl_xor_sync(0xffffffffu, p0, 4);
        p1 += __shfl_xor_sync(0xffffffffu, p1, 4);
        float w0 = __expf(p0);
        float w1 = __expf(p1);
        denom += w0 + w1;
        aggr(acc, tac, w0, v0, e0);
        aggr(acc, tac, w1, v1, e1);
    }
    if (i < s1) {
        int n0 = srcs[i];
        uint4 k0 = *(const uint4*)(kvb + (size_t)n0 * 512 + hoff);
        uint4 v0 = *(const uint4*)(kvb + (size_t)n0 * 512 + 256 + hoff);
        uint4 e0 = *(const uint4*)(ebp + (size_t)i * 64 + li * 8);
        float p0 = dotqk(qv, qev, k0, e0);
        p0 += __shfl_xor_sync(0xffffffffu, p0, 1);
        p0 += __shfl_xor_sync(0xffffffffu, p0, 2);
        p0 += __shfl_xor_sync(0xffffffffu, p0, 4);
        float w0 = __expf(p0);
        denom += w0;
        aggr(acc, tac, w0, v0, e0);
    }
    float inv = (denom > 0.f) ? 1.f / denom : 0.f;
    float qinv = 0.25f * inv;
    {
        uint4 to;
        __nv_bfloat162* top = (__nv_bfloat162*)&to;
#pragma unroll
        for (int t = 0; t < 4; t++)
            top[t] = __floats2bfloat162_rn(tac[2 * t] * qinv, tac[2 * t + 1] * qinv);
        *(uint4*)(t_out + base) = to;
    }
    float red[8];
#pragma unroll
    for (int j = 0; j < 8; j++) {
        float s = acc[j] * inv;
        s += __shfl_xor_sync(0xffffffffu, s, 8);
        s += __shfl_xor_sync(0xffffffffu, s, 16);
        red[j] = 0.25f * s;
    }
    if (g == 0) {
        uint4 ao;
        __nv_bfloat162* aop = (__nv_bfloat162*)&ao;
#pragma unroll
        for (int t = 0; t < 4; t++)
            aop[t] = __floats2bfloat162_rn(red[2 * t], red[2 * t + 1]);
        *(uint4*)(amean + (size_t)n * 64 + li * 8) = ao;
    }
}

// ---------------- mean-pool + classifier + log_softmax ----------------------
__global__ void pool_kernel(const float* __restrict__ h, const int* __restrict__ batch,
                            const float* __restrict__ clsW, const float* __restrict__ clsb,
                            float* __restrict__ out) {
    int gid = blockIdx.x;
    int c = threadIdx.x;
    int lo = 0, hi = Nn;
    while (lo < hi) { int mid = (lo + hi) >> 1; if (batch[mid] < gid) lo = mid + 1; else hi = mid; }
    int start = lo;
    lo = start; hi = Nn;
    while (lo < hi) { int mid = (lo + hi) >> 1; if (batch[mid] < gid + 1) lo = mid + 1; else hi = mid; }
    int end = lo;
    float acc = 0.f;
    for (int r = start; r < end; r++) acc += h[r * HID + c];
    int cntn = end - start;
    float pooled = acc / fmaxf((float)cntn, 1.f);
    __shared__ float ps[HID];
    __shared__ float lg[CLASSES];
    ps[c] = pooled;
    __syncthreads();
    if (c < CLASSES) {
        float s = clsb[c];
        for (int d = 0; d < HID; d++) s += ps[d] * clsW[d * CLASSES + c];
        lg[c] = s;
    }
    __syncthreads();
    if (c == 0) {
        float mm = fmaxf(lg[0], fmaxf(lg[1], lg[2]));
        float se = expf(lg[0] - mm) + expf(lg[1] - mm) + expf(lg[2] - mm);
        float lse = mm + logf(se);
        out[gid * CLASSES + 0] = lg[0] - lse;
        out[gid * CLASSES + 1] = lg[1] - lse;
        out[gid * CLASSES + 2] = lg[2] - lse;
    }
}

// ---------------- host launcher --------------------------------------------
extern "C" void kernel_launch(void* const* d_in, const int* in_sizes, int n_in,
                              void* d_out, int out_size) {
    (void)in_sizes; (void)n_in; (void)out_size;
    const float* x        = (const float*)d_in[0];
    const float* edgeattr = (const float*)d_in[1];
    const float* node_W   = (const float*)d_in[2];
    const float* node_b   = (const float*)d_in[3];
    const float* e1_W     = (const float*)d_in[4];
    const float* e1_b     = (const float*)d_in[5];
    const float* e2_W     = (const float*)d_in[6];
    const float* e2_b     = (const float*)d_in[7];
    const float* Wq       = (const float*)d_in[8];
    const float* bq       = (const float*)d_in[9];
    const float* Wk       = (const float*)d_in[10];
    const float* bk       = (const float*)d_in[11];
    const float* Wv       = (const float*)d_in[12];
    const float* bv       = (const float*)d_in[13];
    const float* We       = (const float*)d_in[14];
    const float* Wskip    = (const float*)d_in[15];
    const float* bskip    = (const float*)d_in[16];
    const float* ln_g     = (const float*)d_in[17];
    const float* ln_b     = (const float*)d_in[18];
    const float* cls_W    = (const float*)d_in[19];
    const float* cls_b    = (const float*)d_in[20];
    const int* edge_index = (const int*)d_in[21];
    const int* batch      = (const int*)d_in[22];
    float* out            = (float*)d_out;

    float *h0, *h1, *qf, *qef, *Bp, *biasp, *Bc;
    unsigned *BfQ, *BfC, *BfH, *BfE;
    __nv_bfloat16 *kvb, *eb, *ebp, *t, *amean;
    int *cnt, *off, *cur, *partial, *basep, *srcs, *eids;
    cudaGetSymbolAddress((void**)&h0, d_h0);
    cudaGetSymbolAddress((void**)&h1, d_h1);
    cudaGetSymbolAddress((void**)&qf, d_qf);
    cudaGetSymbolAddress((void**)&qef, d_qef);
    cudaGetSymbolAddress((void**)&kvb, d_kvb);
    cudaGetSymbolAddress((void**)&eb, d_eb);
    cudaGetSymbolAddress((void**)&ebp, d_ebp);
    cudaGetSymbolAddress((void**)&t, d_t);
    cudaGetSymbolAddress((void**)&amean, d_amean);
    cudaGetSymbolAddress((void**)&Bp, d_Bp);
    cudaGetSymbolAddress((void**)&biasp, d_biasp);
    cudaGetSymbolAddress((void**)&Bc, d_Bc);
    cudaGetSymbolAddress((void**)&BfQ, d_BfQ);
    cudaGetSymbolAddress((void**)&BfC, d_BfC);
    cudaGetSymbolAddress((void**)&BfH, d_BfH);
    cudaGetSymbolAddress((void**)&BfE, d_BfE);
    cudaGetSymbolAddress((void**)&cnt, d_cnt);
    cudaGetSymbolAddress((void**)&off, d_off);
    cudaGetSymbolAddress((void**)&cur, d_cur);
    cudaGetSymbolAddress((void**)&partial, d_partial);
    cudaGetSymbolAddress((void**)&basep, d_base);
    cudaGetSymbolAddress((void**)&srcs, d_srcs);
    cudaGetSymbolAddress((void**)&eids, d_eids);

    // ---- multi-stream prologue: CSR (s3), packs (s1), gemm_h (s4), edge MLP (s2)
    cudaStream_t s1, s2, s3, s4;
    cudaStreamCreateWithFlags(&s1, cudaStreamNonBlocking);
    cudaStreamCreateWithFlags(&s2, cudaStreamNonBlocking);
    cudaStreamCreateWithFlags(&s3, cudaStreamNonBlocking);
    cudaStreamCreateWithFlags(&s4, cudaStreamNonBlocking);
    cudaEvent_t eFork, e1, e2, e3, e4;
    cudaEventCreateWithFlags(&eFork, cudaEventDisableTiming);
    cudaEventCreateWithFlags(&e1, cudaEventDisableTiming);
    cudaEventCreateWithFlags(&e2, cudaEventDisableTiming);
    cudaEventCreateWithFlags(&e3, cudaEventDisableTiming);
    cudaEventCreateWithFlags(&e4, cudaEventDisableTiming);

    cudaEventRecord(eFork, 0);
    cudaStreamWaitEvent(s1, eFork, 0);
    cudaStreamWaitEvent(s2, eFork, 0);
    cudaStreamWaitEvent(s3, eFork, 0);
    cudaStreamWaitEvent(s4, eFork, 0);

    // branch 3 (s3): CSR build
    zero_int_kernel<<<(Nn + 255) / 256, 256, 0, s3>>>(cnt, Nn);
    count_kernel<<<(Ee + 255) / 256, 256, 0, s3>>>(edge_index, cnt);
    scan_partial_kernel<<<SCAN_BLOCKS, 256, 0, s3>>>(cnt, partial);
    scan_base_kernel<<<1, 32, 0, s3>>>(partial, basep, off);
    scan_final_kernel<<<SCAN_BLOCKS, SCAN_CHUNK, 0, s3>>>(cnt, basep, off, cur);
    scatter_kernel<<<(Ee + 255) / 256, 256, 0, s3>>>(edge_index, cur, srcs, eids);
    cudaEventRecord(e3, s3);

    // branch 1 (s1): weight packs only
    {
        int n1 = LAYERS * 65536 + LAYERS * 320 * 64;
        pack_stage1<<<(n1 + 255) / 256, 256, 0, s1>>>(Wq, bq, Wk, bk, Wv, bv, We, Wskip,
                                                      Bp, biasp, Bc);
        int n2 = LAYERS * 65536 + LAYERS * 20480;
        pack_stage2<<<(n2 + 255) / 256, 256, 0, s1>>>(Bp, Bc, BfQ, BfC);
    }
    cudaEventRecord(e1, s1);

    // branch 4 (s4): node projection (independent of packs)
    pack_frag<<<(128 * 64 + 255) / 256, 256, 0, s4>>>(node_W, BfH, 128, 64);
    gemm_h_mma<<<(Nn + 127) / 128, 256, 0, s4>>>(x, BfH, node_b, h0, Nn, NODE_DIM, NODE_DIM);
    cudaEventRecord(e4, s4);

    // branch 2 (s2): edge MLP, then reorder into CSR order (needs CSR too)
    pack_frag<<<(64 * 64 + 255) / 256, 256, 0, s2>>>(e2_W, BfE, 64, 64);
    edge_mlp_mma<<<Ee / 128, 256, 0, s2>>>(edgeattr, e1_W, e1_b, BfE, e2_b, eb);
    cudaStreamWaitEvent(s2, e3, 0);
    reorder_e_kernel<<<(Ee * 8 + 255) / 256, 256, 0, s2>>>(eb, eids, ebp);
    cudaEventRecord(e2, s2);

    // stream 0: qkvqe l0 needs packs (s1) + h0 (s4)
    cudaStreamWaitEvent(0, e1, 0);
    cudaStreamWaitEvent(0, e4, 0);

    float* hc = h0;
    float* hn = h1;
    for (int l = 0; l < LAYERS; l++) {
        gemm_qkvqe_mma<<<dim3((Nn + 127) / 128, 8), 256>>>(hc, BfQ + l * 65536,
                                                           biasp + l * 1024, qf, qef, kvb);
        if (l == 0) {  // attn additionally needs ebp (s2, which includes CSR)
            cudaStreamWaitEvent(0, e2, 0);
        }
        attn_kernel<<<(Nn * 32 + 255) / 256, 256>>>(qf, qef, kvb, ebp, off, srcs, t, amean);
        conv_ln_mma<<<(Nn + 127) / 128, 256>>>(t, hc, BfC + l * 20480, bskip + l * 64,
                                               amean, ln_g + l * 64, ln_b + l * 64, hn);
        float* tmp = hc; hc = hn; hn = tmp;
    }
    pool_kernel<<<GRAPHS, HID>>>(hc, batch, cls_W, cls_b, out);

    cudaStreamDestroy(s1);
    cudaStreamDestroy(s2);
    cudaStreamDestroy(s3);
    cudaStreamDestroy(s4);
    cudaEventDestroy(eFork);
    cudaEventDestroy(e1);
    cudaEventDestroy(e2);
    cudaEventDestroy(e3);
    cudaEventDestroy(e4);
}

// round 14
// speedup vs baseline: 1.0452x; 1.0452x over previous
#include <cuda_runtime.h>
#include <cuda_bf16.h>
#include <math.h>

#define Nn 20000
#define Ee 256000
#define NODE_DIM 128
#define EDGE_DIM 8
#define HID 64
#define HEADS 4
#define HC 256
#define LAYERS 3
#define CLASSES 3
#define GRAPHS 64
#define SCAN_CHUNK 1024
#define SCAN_BLOCKS ((Nn + SCAN_CHUNK - 1) / SCAN_CHUNK)

// ---------------- scratch (static device allocations; no cudaMalloc) -------
__device__ float d_h0[Nn * HID];
__device__ float d_h1[Nn * HID];
__device__ float d_qf[Nn * HC];
__device__ float d_qef[Nn * HC];
__device__ __nv_bfloat16 d_kvb[Nn * 512];         // interleaved [k(256) | v(256)]
__device__ __nv_bfloat16 d_eb[Ee * HID];
__device__ __nv_bfloat16 d_ebp[Ee * HID];         // eb permuted to CSR order
__device__ __nv_bfloat16 d_t[Nn * HC];            // bf16 attention outputs
__device__ __nv_bfloat16 d_amean[Nn * HID];
__device__ float d_Bp[LAYERS * HID * 1024];
__device__ float d_biasp[LAYERS * 1024];
__device__ float d_Bc[LAYERS * 320 * HID];
__device__ unsigned d_BfQ[LAYERS * HID * 1024];   // tf32 frag-order qkvqe B
__device__ unsigned d_BfC[LAYERS * 320 * HID];    // tf32 frag-order conv B
__device__ unsigned d_BfH[NODE_DIM * HID];        // tf32 frag-order node_W
__device__ unsigned d_BfE[HID * HID];             // tf32 frag-order e2_W
__device__ int d_cnt[Nn];
__device__ int d_off[Nn + 1];
__device__ int d_cur[Nn];
__device__ int d_partial[SCAN_BLOCKS];
__device__ int d_base[SCAN_BLOCKS];
__device__ int d_srcs[Ee];
__device__ int d_eids[Ee];

// ---------------- tf32 / mma helpers ---------------------------------------
__device__ __forceinline__ unsigned f2tf(float f) {
    unsigned u;
    asm("cvt.rna.tf32.f32 %0, %1;" : "=r"(u) : "f"(f));
    return u;
}

__device__ __forceinline__ void mma8(float c[4], unsigned a0, unsigned a1, unsigned a2,
                                     unsigned a3, unsigned b0, unsigned b1) {
    asm volatile(
        "mma.sync.aligned.m16n8k8.row.col.f32.tf32.tf32.f32 "
        "{%0,%1,%2,%3}, {%4,%5,%6,%7}, {%8,%9}, {%0,%1,%2,%3};"
        : "+f"(c[0]), "+f"(c[1]), "+f"(c[2]), "+f"(c[3])
        : "r"(a0), "r"(a1), "r"(a2), "r"(a3), "r"(b0), "r"(b1));
}

// stage 128x32 fp32 -> tf32 smem tile (pad 36 => conflict-free frag LDS)
__device__ __forceinline__ void stage_A(const float* __restrict__ A, int lda, int bm, int M,
                                        int k0, unsigned (*As)[36], int tid) {
    int ar = tid >> 1, ac = (tid & 1) * 16;
    int row = bm + ar;
    const float* Ap = A + (size_t)row * lda + k0 + ac;
    bool ok = row < M;
#pragma unroll
    for (int j = 0; j < 4; j++) {
        float4 v = ok ? *(const float4*)(Ap + 4 * j) : make_float4(0.f, 0.f, 0.f, 0.f);
        As[ar][ac + 4 * j + 0] = f2tf(v.x);
        As[ar][ac + 4 * j + 1] = f2tf(v.y);
        As[ar][ac + 4 * j + 2] = f2tf(v.z);
        As[ar][ac + 4 * j + 3] = f2tf(v.w);
    }
}

// stage 128x32 bf16 -> tf32 smem tile
__device__ __forceinline__ void stage_Abf(const __nv_bfloat16* __restrict__ A, int lda, int bm,
                                          int M, int k0, unsigned (*As)[36], int tid) {
    int ar = tid >> 1, ac = (tid & 1) * 16;
    int row = bm + ar;
    const __nv_bfloat16* Ap = A + (size_t)row * lda + k0 + ac;
    bool ok = row < M;
    uint4 z = make_uint4(0, 0, 0, 0);
    uint4 r0 = ok ? *(const uint4*)Ap : z;
    uint4 r1 = ok ? *(const uint4*)(Ap + 8) : z;
    const __nv_bfloat162* p0 = (const __nv_bfloat162*)&r0;
    const __nv_bfloat162* p1 = (const __nv_bfloat162*)&r1;
#pragma unroll
    for (int j = 0; j < 4; j++) {
        float2 f0 = __bfloat1622float2(p0[j]);
        float2 f1 = __bfloat1622float2(p1[j]);
        As[ar][ac + 2 * j + 0] = f2tf(f0.x);
        As[ar][ac + 2 * j + 1] = f2tf(f0.y);
        As[ar][ac + 8 + 2 * j + 0] = f2tf(f1.x);
        As[ar][ac + 8 + 2 * j + 1] = f2tf(f1.y);
    }
}

// one 32-wide K chunk: 4 k-steps of m16n8k8 across warp's 32x32 tile
__device__ __forceinline__ void mma_stage(const unsigned (*As)[36], const uint2* __restrict__ bst,
                                          float acc[2][4][4], int wm, int wn, int g, int tg,
                                          int lane) {
#pragma unroll
    for (int s = 0; s < 4; s++) {
        unsigned a[2][4];
#pragma unroll
        for (int t = 0; t < 2; t++) {
            int r = wm * 32 + t * 16 + g;
            a[t][0] = As[r][s * 8 + tg];
            a[t][1] = As[r + 8][s * 8 + tg];
            a[t][2] = As[r][s * 8 + tg + 4];
            a[t][3] = As[r + 8][s * 8 + tg + 4];
        }
        const uint2* bp = bst + ((s * 2 + wn) * 4) * 32 + lane;
#pragma unroll
        for (int u = 0; u < 4; u++) {
            uint2 b = bp[u * 32];
#pragma unroll
            for (int t = 0; t < 2; t++)
                mma8(acc[t][u], a[t][0], a[t][1], a[t][2], a[t][3], b.x, b.y);
        }
    }
}

// ---------------- CSR build -------------------------------------------------
__global__ void zero_int_kernel(int* p, int n) {
    int i = blockIdx.x * blockDim.x + threadIdx.x;
    if (i < n) p[i] = 0;
}

__global__ void count_kernel(const int* __restrict__ edge_index, int* __restrict__ cnt) {
    int i = blockIdx.x * blockDim.x + threadIdx.x;
    if (i < Ee) atomicAdd(&cnt[edge_index[Ee + i]], 1);
}

__global__ void scan_partial_kernel(const int* __restrict__ cnt, int* __restrict__ partial) {
    __shared__ int sh[256];
    int b = blockIdx.x, tid = threadIdx.x;
    int base = b * SCAN_CHUNK;
    int s = 0;
#pragma unroll
    for (int j = 0; j < SCAN_CHUNK / 256; j++) {
        int i = base + j * 256 + tid;
        s += (i < Nn) ? cnt[i] : 0;
    }
    sh[tid] = s;
    __syncthreads();
    for (int st = 128; st >= 1; st >>= 1) {
        if (tid < st) sh[tid] += sh[tid + st];
        __syncthreads();
    }
    if (tid == 0) partial[b] = sh[0];
}

__global__ void scan_base_kernel(const int* __restrict__ partial, int* __restrict__ base,
                                 int* __restrict__ off) {
    if (threadIdx.x == 0) {
        int run = 0;
        for (int i = 0; i < SCAN_BLOCKS; i++) { base[i] = run; run += partial[i]; }
        off[Nn] = run;
    }
}

__global__ void scan_final_kernel(const int* __restrict__ cnt, const int* __restrict__ base,
                                  int* __restrict__ off, int* __restrict__ cur) {
    __shared__ int sh[SCAN_CHUNK];
    int b = blockIdx.x, tid = threadIdx.x;
    int i = b * SCAN_CHUNK + tid;
    int v = (i < Nn) ? cnt[i] : 0;
    sh[tid] = v;
    __syncthreads();
    for (int s = 1; s < SCAN_CHUNK; s <<= 1) {
        int t2 = (tid >= s) ? sh[tid - s] : 0;
        __syncthreads();
        sh[tid] += t2;
        __syncthreads();
    }
    if (i < Nn) {
        int excl = sh[tid] - v + base[b];
        off[i] = excl;
        cur[i] = excl;
    }
}

__global__ void scatter_kernel(const int* __restrict__ edge_index, int* __restrict__ cur,
                               int* __restrict__ srcs, int* __restrict__ eids) {
    int i = blockIdx.x * blockDim.x + threadIdx.x;
    if (i < Ee) {
        int src = edge_index[i];
        int dst = edge_index[Ee + i];
        int pos = atomicAdd(&cur[dst], 1);
        srcs[pos] = src;
        eids[pos] = i;
    }
}

// permute eb into CSR order: ebp[i] = eb[eids[i]]
__global__ void reorder_e_kernel(const __nv_bfloat16* __restrict__ eb,
                                 const int* __restrict__ eids,
                                 __nv_bfloat16* __restrict__ ebp) {
    int idx = blockIdx.x * blockDim.x + threadIdx.x;
    if (idx >= Ee * 8) return;
    int i = idx >> 3;
    int c = (idx & 7) * 8;
    int eid = eids[i];
    *(uint4*)(ebp + (size_t)i * 64 + c) = *(const uint4*)(eb + (size_t)eid * 64 + c);
}

// ---------------- weight packing (fused) -------------------------------------
__global__ void pack_stage1(const float* __restrict__ Wq, const float* __restrict__ bq,
                            const float* __restrict__ Wk, const float* __restrict__ bk,
                            const float* __restrict__ Wv, const float* __restrict__ bv,
                            const float* __restrict__ We, const float* __restrict__ Wskip,
                            float* __restrict__ Bp, float* __restrict__ biasp,
                            float* __restrict__ Bc) {
    int idx = blockIdx.x * blockDim.x + threadIdx.x;
    if (idx < LAYERS * 65536) {
        int l = idx >> 16;
        int rem = idx & 65535;
        int j = rem >> 10;
        int col = rem & 1023;
        const float* Wql = Wq + l * 16384;
        const float* Wkl = Wk + l * 16384;
        const float* Wvl = Wv + l * 16384;
        const float* Wel = We + l * 16384;
        float v;
        if (col < 256) v = Wql[j * 256 + col];
        else if (col < 512) v = Wkl[j * 256 + col - 256];
        else if (col < 768) v = Wvl[j * 256 + col - 512];
        else {
            int d2 = col - 768; int h = d2 >> 6; int d = d2 & 63;
            float s = 0.f;
            for (int c = 0; c < 64; c++)
                s += Wql[j * 256 + h * 64 + c] * Wel[d * 256 + h * 64 + c];
            v = s;
        }
        Bp[idx] = v;
        if (j == 0) {
            float bvv;
            if (col < 256) bvv = bq[l * 256 + col];
            else if (col < 512) bvv = bk[l * 256 + col - 256];
            else if (col < 768) bvv = bv[l * 256 + col - 512];
            else {
                int d2 = col - 768; int h = d2 >> 6; int d = d2 & 63;
                float s = 0.f;
                for (int c = 0; c < 64; c++)
                    s += bq[l * 256 + h * 64 + c] * Wel[d * 256 + h * 64 + c];
                bvv = s;
            }
            biasp[l * 1024 + col] = bvv;
        }
    } else {
        int j = idx - LAYERS * 65536;
        if (j >= LAYERS * 320 * 64) return;
        int l = j / (320 * 64);
        int r = (j >> 6) % 320;
        int c = j & 63;
        float v;
        if (r < 256) {
            int h = r >> 6, d = r & 63;
            v = We[l * 16384 + d * 256 + h * 64 + c];
        } else {
            v = Wskip[l * 4096 + (r - 256) * 64 + c];
        }
        Bc[j] = v;
    }
}

__device__ __forceinline__ void frag_pack(const float* __restrict__ B, unsigned* __restrict__ out,
                                          int idx, int K, int Ncols) {
    int ks_total = K >> 3;
    int p = idx & 1;
    int lane = (idx >> 1) & 31;
    int u = (idx >> 6) & 3;
    int wn = (idx >> 8) & 1;
    int rest = idx >> 9;
    int ks = rest % ks_total;
    int bnb = rest / ks_total;
    int k = ks * 8 + (lane & 3) + 4 * p;
    int n = bnb * 64 + wn * 32 + u * 8 + (lane >> 2);
    out[idx] = f2tf(B[k * Ncols + n]);
}

__global__ void pack_frag(const float* __restrict__ B, unsigned* __restrict__ out,
                          int K, int Ncols) {
    int idx = blockIdx.x * blockDim.x + threadIdx.x;
    if (idx < K * Ncols) frag_pack(B, out, idx, K, Ncols);
}

__global__ void pack_stage2(const float* __restrict__ Bp, const float* __restrict__ Bc,
                            unsigned* __restrict__ BfQ, unsigned* __restrict__ BfC) {
    int idx = blockIdx.x * blockDim.x + threadIdx.x;
    if (idx < LAYERS * 65536) {
        int l = idx >> 16;
        frag_pack(Bp + l * 65536, BfQ + l * 65536, idx & 65535, 64, 1024);
    } else {
        int j = idx - LAYERS * 65536;
        if (j >= LAYERS * 20480) return;
        int l = j / 20480;
        frag_pack(Bc + l * 20480, BfC + l * 20480, j % 20480, 320, 64);
    }
}

// ---------------- node projection (tf32 MMA, double-buffered) ---------------
__global__ void gemm_h_mma(const float* __restrict__ A, const unsigned* __restrict__ Bf,
                           const float* __restrict__ bias, float* __restrict__ C,
                           int M, int K, int lda) {
    __shared__ unsigned As[2][128][36];
    float acc[2][4][4] = {};
    int bm = blockIdx.x * 128;
    int tid = threadIdx.x, w = tid >> 5, lane = tid & 31;
    int wm = w & 3, wn = w >> 2, g = lane >> 2, tg = lane & 3;
    int nst = K >> 5;
    stage_A(A, lda, bm, M, 0, As[0], tid);
    __syncthreads();
    for (int st = 0; st < nst; st++) {
        int cb = st & 1;
        if (st + 1 < nst) stage_A(A, lda, bm, M, (st + 1) * 32, As[cb ^ 1], tid);
        mma_stage(As[cb], (const uint2*)Bf + st * 1024, acc, wm, wn, g, tg, lane);
        __syncthreads();
    }
#pragma unroll
    for (int u = 0; u < 4; u++) {
        int col = wn * 32 + u * 8 + 2 * tg;
        float2 bb = *(const float2*)(bias + col);
#pragma unroll
        for (int t = 0; t < 2; t++) {
            int row = bm + wm * 32 + t * 16 + g;
            if (row < M) {
                float2 o = {acc[t][u][0] + bb.x, acc[t][u][1] + bb.y};
                *(float2*)(C + (size_t)row * 64 + col) = o;
            }
            if (row + 8 < M) {
                float2 o = {acc[t][u][2] + bb.x, acc[t][u][3] + bb.y};
                *(float2*)(C + (size_t)(row + 8) * 64 + col) = o;
            }
        }
    }
}

// ---------------- fused QKVQE (tf32 MMA): A staged once per 4 n-blocks ------
// gridDim.y = 4; block handles bn = 4*blockIdx.y + {0..3}; j-loop NOT unrolled
// so acc registers are reused across iterations (R8's failure was the unroll).
__global__ void __launch_bounds__(256)
gemm_qkvqe_mma(const float* __restrict__ h, const unsigned* __restrict__ BfQ,
               const float* __restrict__ biasp,
               float* __restrict__ qf, float* __restrict__ qef,
               __nv_bfloat16* __restrict__ kvb) {
    __shared__ unsigned As[2][128][36];
    int bm = blockIdx.x * 128;
    int tid = threadIdx.x, w = tid >> 5, lane = tid & 31;
    int wm = w & 3, wn = w >> 2, g = lane >> 2, tg = lane & 3;
    stage_A(h, 64, bm, Nn, 0, As[0], tid);
    stage_A(h, 64, bm, Nn, 32, As[1], tid);
    __syncthreads();
#pragma unroll 1
    for (int j = 0; j < 4; j++) {
        int bn = blockIdx.y * 4 + j;
        const uint2* Bfb = (const uint2*)BfQ + bn * 2048;
        float acc[2][4][4] = {};
        mma_stage(As[0], Bfb, acc, wm, wn, g, tg, lane);
        mma_stage(As[1], Bfb + 1024, acc, wm, wn, g, tg, lane);
        int sec = bn >> 2;
#pragma unroll
        for (int u = 0; u < 4; u++) {
            int colL = wn * 32 + u * 8 + 2 * tg;
            float2 bb = *(const float2*)(biasp + bn * 64 + colL);
            int coff = (bn & 3) * 64 + colL;
#pragma unroll
            for (int t = 0; t < 2; t++) {
#pragma unroll
                for (int hh = 0; hh < 2; hh++) {
                    int row = bm + wm * 32 + t * 16 + g + 8 * hh;
                    if (row >= Nn) continue;
                    float v0 = acc[t][u][2 * hh + 0] + bb.x;
                    float v1 = acc[t][u][2 * hh + 1] + bb.y;
                    if (sec == 0) {
                        float2 o = {v0, v1};
                        *(float2*)(qf + (size_t)row * 256 + coff) = o;
                    } else if (sec == 3) {
                        float2 o = {v0, v1};
                        *(float2*)(qef + (size_t)row * 256 + coff) = o;
                    } else {
                        __nv_bfloat16* dst = kvb + (size_t)row * 512 + (sec == 2 ? 256 : 0) + coff;
                        *(__nv_bfloat162*)dst = __floats2bfloat162_rn(v0, v1);
                    }
                }
            }
        }
    }
}

// ---------------- fused conv (tf32 MMA, double-buffered) + LN + relu --------
__global__ void conv_ln_mma(const __nv_bfloat16* __restrict__ t, const float* __restrict__ hres,
                            const unsigned* __restrict__ BfC, const float* __restrict__ bskip,
                            const __nv_bfloat16* __restrict__ amean,
                            const float* __restrict__ gam,
                            const float* __restrict__ bet, float* __restrict__ hout) {
    __shared__ unsigned As[2][128][36];
    __shared__ float Ssum[128][2];
    __shared__ float Ssq[128][2];
    float acc[2][4][4] = {};
    int bm = blockIdx.x * 128;
    int tid = threadIdx.x, w = tid >> 5, lane = tid & 31;
    int wm = w & 3, wn = w >> 2, g = lane >> 2, tg = lane & 3;
    stage_Abf(t, 256, bm, Nn, 0, As[0], tid);
    __syncthreads();
    for (int st = 0; st < 10; st++) {
        int cb = st & 1;
        int nx = st + 1;
        if (nx < 8) stage_Abf(t, 256, bm, Nn, nx * 32, As[cb ^ 1], tid);
        else if (nx < 10) stage_A(hres, 64, bm, Nn, (nx - 8) * 32, As[cb ^ 1], tid);
        mma_stage(As[cb], (const uint2*)BfC + st * 1024, acc, wm, wn, g, tg, lane);
        __syncthreads();
    }
    float xs[2][4][4];
#pragma unroll
    for (int u = 0; u < 4; u++) {
        int col = wn * 32 + u * 8 + 2 * tg;
        float2 bb = *(const float2*)(bskip + col);
#pragma unroll
        for (int t2 = 0; t2 < 2; t2++) {
#pragma unroll
            for (int hh = 0; hh < 2; hh++) {
                int row = bm + wm * 32 + t2 * 16 + g + 8 * hh;
                float2 am = make_float2(0.f, 0.f), hr = make_float2(0.f, 0.f);
                if (row < Nn) {
                    am = __bfloat1622float2(
                        *(const __nv_bfloat162*)(amean + (size_t)row * 64 + col));
                    hr = *(const float2*)(hres + (size_t)row * 64 + col);
                }
                xs[t2][u][2 * hh + 0] = acc[t2][u][2 * hh + 0] + bb.x + am.x + hr.x;
                xs[t2][u][2 * hh + 1] = acc[t2][u][2 * hh + 1] + bb.y + am.y + hr.y;
            }
        }
    }
#pragma unroll
    for (int t2 = 0; t2 < 2; t2++) {
#pragma unroll
        for (int hh = 0; hh < 2; hh++) {
            float s = 0.f, q = 0.f;
#pragma unroll
            for (int u = 0; u < 4; u++) {
                float a = xs[t2][u][2 * hh + 0], b = xs[t2][u][2 * hh + 1];
                s += a + b;
                q += a * a + b * b;
            }
            s += __shfl_xor_sync(0xffffffffu, s, 1);
            s += __shfl_xor_sync(0xffffffffu, s, 2);
            q += __shfl_xor_sync(0xffffffffu, q, 1);
            q += __shfl_xor_sync(0xffffffffu, q, 2);
            if (tg == 0) {
                int lr = wm * 32 + t2 * 16 + g + 8 * hh;
                Ssum[lr][wn] = s;
                Ssq[lr][wn] = q;
            }
        }
    }
    __syncthreads();
#pragma unroll
    for (int t2 = 0; t2 < 2; t2++) {
#pragma unroll
        for (int hh = 0; hh < 2; hh++) {
            int lr = wm * 32 + t2 * 16 + g + 8 * hh;
            int row = bm + lr;
            float m = (Ssum[lr][0] + Ssum[lr][1]) * (1.f / 64.f);
            float var = (Ssq[lr][0] + Ssq[lr][1]) * (1.f / 64.f) - m * m;
            float rs = rsqrtf(var + 1e-5f);
            if (row >= Nn) continue;
#pragma unroll
            for (int u = 0; u < 4; u++) {
                int col = wn * 32 + u * 8 + 2 * tg;
                float2 gg = *(const float2*)(gam + col);
                float2 b2 = *(const float2*)(bet + col);
                float2 o;
                o.x = fmaxf((xs[t2][u][2 * hh + 0] - m) * rs * gg.x + b2.x, 0.f);
                o.y = fmaxf((xs[t2][u][2 * hh + 1] - m) * rs * gg.y + b2.y, 0.f);
                *(float2*)(hout + (size_t)row * 64 + col) = o;
            }
        }
    }
}

// ---------------- fused edge MLP (tf32 MMA): eb = bf16(relu(ea@W1+b1)@W2+b2)
__global__ void edge_mlp_mma(const float* __restrict__ ea, const float* __restrict__ W1,
                             const float* __restrict__ b1, const unsigned* __restrict__ BfE,
                             const float* __restrict__ b2, __nv_bfloat16* __restrict__ eb) {
    __shared__ unsigned As[128][68];
    __shared__ float W1s[EDGE_DIM * HID];
    __shared__ float b1s[HID];
    int tid = threadIdx.x, w = tid >> 5, lane = tid & 31;
    int wm = w & 3, wn = w >> 2, g = lane >> 2, tg = lane & 3;
    int be = blockIdx.x * 128;
    for (int i = tid; i < EDGE_DIM * HID; i += 256) W1s[i] = W1[i];
    if (tid < HID) b1s[tid] = b1[tid];
    __syncthreads();
    {
        int r = tid >> 1, half = tid & 1;
        float av[EDGE_DIM];
        const float* eap = ea + (size_t)(be + r) * EDGE_DIM;
#pragma unroll
        for (int d = 0; d < EDGE_DIM; d++) av[d] = eap[d];
#pragma unroll
        for (int c = 0; c < 32; c++) {
            int col = half * 32 + c;
            float s = b1s[col];
#pragma unroll
            for (int d = 0; d < EDGE_DIM; d++) s += av[d] * W1s[d * HID + col];
            As[r][col] = f2tf(fmaxf(s, 0.f));
        }
    }
    __syncthreads();
    float acc[2][4][4] = {};
#pragma unroll
    for (int st = 0; st < 2; st++) {
#pragma unroll
        for (int s = 0; s < 4; s++) {
            unsigned a[2][4];
#pragma unroll
            for (int t = 0; t < 2; t++) {
                int r = wm * 32 + t * 16 + g;
                a[t][0] = As[r][st * 32 + s * 8 + tg];
                a[t][1] = As[r + 8][st * 32 + s * 8 + tg];
                a[t][2] = As[r][st * 32 + s * 8 + tg + 4];
                a[t][3] = As[r + 8][st * 32 + s * 8 + tg + 4];
            }
            const uint2* bp = (const uint2*)BfE + st * 1024 + ((s * 2 + wn) * 4) * 32 + lane;
#pragma unroll
            for (int u = 0; u < 4; u++) {
                uint2 b = bp[u * 32];
#pragma unroll
                for (int t = 0; t < 2; t++)
                    mma8(acc[t][u], a[t][0], a[t][1], a[t][2], a[t][3], b.x, b.y);
            }
        }
    }
#pragma unroll
    for (int u = 0; u < 4; u++) {
        int col = wn * 32 + u * 8 + 2 * tg;
        float2 bb = *(const float2*)(b2 + col);
#pragma unroll
        for (int t = 0; t < 2; t++) {
#pragma unroll
            for (int hh = 0; hh < 2; hh++) {
                int row = be + wm * 32 + t * 16 + g + 8 * hh;
                float v0 = acc[t][u][2 * hh + 0] + bb.x;
                float v1 = acc[t][u][2 * hh + 1] + bb.y;
                *(__nv_bfloat162*)(eb + (size_t)row * HID + col) = __floats2bfloat162_rn(v0, v1);
            }
        }
    }
}

// ---------------- per-node attention: raw bf16 regs, CSR-ordered e ----------
__device__ __forceinline__ float dotqk(const float* qv, const float* qev, uint4 kr, uint4 er) {
    const __nv_bfloat162* kp = (const __nv_bfloat162*)&kr;
    const __nv_bfloat162* ep = (const __nv_bfloat162*)&er;
    float p = 0.f;
#pragma unroll
    for (int t = 0; t < 4; t++) {
        float2 kf = __bfloat1622float2(kp[t]);
        float2 ef = __bfloat1622float2(ep[t]);
        p += qv[2 * t] * kf.x + qv[2 * t + 1] * kf.y;
        p += qev[2 * t] * ef.x + qev[2 * t + 1] * ef.y;
    }
    return p;
}

__device__ __forceinline__ void aggr(float* acc, float* tac, float wgt, uint4 vr, uint4 er) {
    const __nv_bfloat162* vp = (const __nv_bfloat162*)&vr;
    const __nv_bfloat162* ep = (const __nv_bfloat162*)&er;
#pragma unroll
    for (int t = 0; t < 4; t++) {
        float2 vf = __bfloat1622float2(vp[t]);
        float2 ef = __bfloat1622float2(ep[t]);
        acc[2 * t + 0] += wgt * vf.x;
        acc[2 * t + 1] += wgt * vf.y;
        tac[2 * t + 0] += wgt * ef.x;
        tac[2 * t + 1] += wgt * ef.y;
    }
}

__global__ void __launch_bounds__(256, 4)
attn_kernel(const float* __restrict__ qf, const float* __restrict__ qef,
            const __nv_bfloat16* __restrict__ kvb, const __nv_bfloat16* __restrict__ ebp,
            const int* __restrict__ off, const int* __restrict__ srcs,
            __nv_bfloat16* __restrict__ t_out, __nv_bfloat16* __restrict__ amean) {
    int warp = (blockIdx.x * blockDim.x + threadIdx.x) >> 5;
    if (warp >= Nn) return;
    int lane = threadIdx.x & 31;
    int g = lane >> 3;
    int li = lane & 7;
    int n = warp;
    int base = n * HC + g * 64 + li * 8;
    int hoff = g * 64 + li * 8;
    float qv[8], qev[8];
    {
        // fold softmax scale (1/8, exact power of 2) into q registers
        float4 a = *(const float4*)(qf + base);
        float4 b = *(const float4*)(qf + base + 4);
        qv[0]=a.x*0.125f; qv[1]=a.y*0.125f; qv[2]=a.z*0.125f; qv[3]=a.w*0.125f;
        qv[4]=b.x*0.125f; qv[5]=b.y*0.125f; qv[6]=b.z*0.125f; qv[7]=b.w*0.125f;
        float4 c = *(const float4*)(qef + base);
        float4 d = *(const float4*)(qef + base + 4);
        qev[0]=c.x*0.125f; qev[1]=c.y*0.125f; qev[2]=c.z*0.125f; qev[3]=c.w*0.125f;
        qev[4]=d.x*0.125f; qev[5]=d.y*0.125f; qev[6]=d.z*0.125f; qev[7]=d.w*0.125f;
    }

    int s0 = off[n], s1 = off[n + 1];
    float denom = 0.f;
    float acc[8] = {}, tac[8] = {};

    int i = s0;
    for (; i + 2 <= s1; i += 2) {
        int n0 = srcs[i];
        int n1 = srcs[i + 1];
        uint4 k0 = *(const uint4*)(kvb + (size_t)n0 * 512 + hoff);
        uint4 k1 = *(const uint4*)(kvb + (size_t)n1 * 512 + hoff);
        uint4 v0 = *(const uint4*)(kvb + (size_t)n0 * 512 + 256 + hoff);
        uint4 v1 = *(const uint4*)(kvb + (size_t)n1 * 512 + 256 + hoff);
        uint4 e0 = *(const uint4*)(ebp + (size_t)i * 64 + li * 8);
        uint4 e1 = *(const uint4*)(ebp + (size_t)(i + 1) * 64 + li * 8);
        float p0 = dotqk(qv, qev, k0, e0);
        float p1 = dotqk(qv, qev, k1, e1);
        p0 += __shfl_xor_sync(0xffffffffu, p0, 1);
        p1 += __shfl_xor_sync(0xffffffffu, p1, 1);
        p0 += __shfl_xor_sync(0xffffffffu, p0, 2);
        p1 += __shfl_xor_sync(0xffffffffu, p1, 2);
        p0 += __shfl_xor_sync(0xffffffffu, p0, 4);
        p1 += __shfl_xor_sync(0xffffffffu, p1, 4);
        float w0 = __expf(p0);
        float w1 = __expf(p1);
        denom += w0 + w1;
        aggr(acc, tac, w0, v0, e0);
        aggr(acc, tac, w1, v1, e1);
    }
    if (i < s1) {
        int n0 = srcs[i];
        uint4 k0 = *(const uint4*)(kvb + (size_t)n0 * 512 + hoff);
        uint4 v0 = *(const uint4*)(kvb + (size_t)n0 * 512 + 256 + hoff);
        uint4 e0 = *(const uint4*)(ebp + (size_t)i * 64 + li * 8);
        float p0 = dotqk(qv, qev, k0, e0);
        p0 += __shfl_xor_sync(0xffffffffu, p0, 1);
        p0 += __shfl_xor_sync(0xffffffffu, p0, 2);
        p0 += __shfl_xor_sync(0xffffffffu, p0, 4);
        float w0 = __expf(p0);
        denom += w0;
        aggr(acc, tac, w0, v0, e0);
    }
    float inv = (denom > 0.f) ? 1.f / denom : 0.f;
    float qinv = 0.25f * inv;
    {
        uint4 to;
        __nv_bfloat162* top = (__nv_bfloat162*)&to;
#pragma unroll
        for (int t = 0; t < 4; t++)
            top[t] = __floats2bfloat162_rn(tac[2 * t] * qinv, tac[2 * t + 1] * qinv);
        *(uint4*)(t_out + base) = to;
    }
    float red[8];
#pragma unroll
    for (int j = 0; j < 8; j++) {
        float s = acc[j] * inv;
        s += __shfl_xor_sync(0xffffffffu, s, 8);
        s += __shfl_xor_sync(0xffffffffu, s, 16);
        red[j] = 0.25f * s;
    }
    if (g == 0) {
        uint4 ao;
        __nv_bfloat162* aop = (__nv_bfloat162*)&ao;
#pragma unroll
        for (int t = 0; t < 4; t++)
            aop[t] = __floats2bfloat162_rn(red[2 * t], red[2 * t + 1]);
        *(uint4*)(amean + (size_t)n * 64 + li * 8) = ao;
    }
}

// ---------------- mean-pool + classifier + log_softmax ----------------------
__global__ void pool_kernel(const float* __restrict__ h, const int* __restrict__ batch,
                            const float* __restrict__ clsW, const float* __restrict__ clsb,
                            float* __restrict__ out) {
    int gid = blockIdx.x;
    int c = threadIdx.x;
    int lo = 0, hi = Nn;
    while (lo < hi) { int mid = (lo + hi) >> 1; if (batch[mid] < gid) lo = mid + 1; else hi = mid; }
    int start = lo;
    lo = start; hi = Nn;
    while (lo < hi) { int mid = (lo + hi) >> 1; if (batch[mid] < gid + 1) lo = mid + 1; else hi = mid; }
    int end = lo;
    float acc = 0.f;
    for (int r = start; r < end; r++) acc += h[r * HID + c];
    int cntn = end - start;
    float pooled = acc / fmaxf((float)cntn, 1.f);
    __shared__ float ps[HID];
    __shared__ float lg[CLASSES];
    ps[c] = pooled;
    __syncthreads();
    if (c < CLASSES) {
        float s = clsb[c];
        for (int d = 0; d < HID; d++) s += ps[d] * clsW[d * CLASSES + c];
        lg[c] = s;
    }
    __syncthreads();
    if (c == 0) {
        float mm = fmaxf(lg[0], fmaxf(lg[1], lg[2]));
        float se = expf(lg[0] - mm) + expf(lg[1] - mm) + expf(lg[2] - mm);
        float lse = mm + logf(se);
        out[gid * CLASSES + 0] = lg[0] - lse;
        out[gid * CLASSES + 1] = lg[1] - lse;
        out[gid * CLASSES + 2] = lg[2] - lse;
    }
}

// ---------------- host launcher --------------------------------------------
extern "C" void kernel_launch(void* const* d_in, const int* in_sizes, int n_in,
                              void* d_out, int out_size) {
    (void)in_sizes; (void)n_in; (void)out_size;
    const float* x        = (const float*)d_in[0];
    const float* edgeattr = (const float*)d_in[1];
    const float* node_W   = (const float*)d_in[2];
    const float* node_b   = (const float*)d_in[3];
    const float* e1_W     = (const float*)d_in[4];
    const float* e1_b     = (const float*)d_in[5];
    const float* e2_W     = (const float*)d_in[6];
    const float* e2_b     = (const float*)d_in[7];
    const float* Wq       = (const float*)d_in[8];
    const float* bq       = (const float*)d_in[9];
    const float* Wk       = (const float*)d_in[10];
    const float* bk       = (const float*)d_in[11];
    const float* Wv       = (const float*)d_in[12];
    const float* bv       = (const float*)d_in[13];
    const float* We       = (const float*)d_in[14];
    const float* Wskip    = (const float*)d_in[15];
    const float* bskip    = (const float*)d_in[16];
    const float* ln_g     = (const float*)d_in[17];
    const float* ln_b     = (const float*)d_in[18];
    const float* cls_W    = (const float*)d_in[19];
    const float* cls_b    = (const float*)d_in[20];
    const int* edge_index = (const int*)d_in[21];
    const int* batch      = (const int*)d_in[22];
    float* out            = (float*)d_out;

    float *h0, *h1, *qf, *qef, *Bp, *biasp, *Bc;
    unsigned *BfQ, *BfC, *BfH, *BfE;
    __nv_bfloat16 *kvb, *eb, *ebp, *t, *amean;
    int *cnt, *off, *cur, *partial, *basep, *srcs, *eids;
    cudaGetSymbolAddress((void**)&h0, d_h0);
    cudaGetSymbolAddress((void**)&h1, d_h1);
    cudaGetSymbolAddress((void**)&qf, d_qf);
    cudaGetSymbolAddress((void**)&qef, d_qef);
    cudaGetSymbolAddress((void**)&kvb, d_kvb);
    cudaGetSymbolAddress((void**)&eb, d_eb);
    cudaGetSymbolAddress((void**)&ebp, d_ebp);
    cudaGetSymbolAddress((void**)&t, d_t);
    cudaGetSymbolAddress((void**)&amean, d_amean);
    cudaGetSymbolAddress((void**)&Bp, d_Bp);
    cudaGetSymbolAddress((void**)&biasp, d_biasp);
    cudaGetSymbolAddress((void**)&Bc, d_Bc);
    cudaGetSymbolAddress((void**)&BfQ, d_BfQ);
    cudaGetSymbolAddress((void**)&BfC, d_BfC);
    cudaGetSymbolAddress((void**)&BfH, d_BfH);
    cudaGetSymbolAddress((void**)&BfE, d_BfE);
    cudaGetSymbolAddress((void**)&cnt, d_cnt);
    cudaGetSymbolAddress((void**)&off, d_off);
    cudaGetSymbolAddress((void**)&cur, d_cur);
    cudaGetSymbolAddress((void**)&partial, d_partial);
    cudaGetSymbolAddress((void**)&basep, d_base);
    cudaGetSymbolAddress((void**)&srcs, d_srcs);
    cudaGetSymbolAddress((void**)&eids, d_eids);

    // ---- multi-stream prologue: CSR (s3), packs (s1), gemm_h (s4), edge MLP (s2)
    cudaStream_t s1, s2, s3, s4;
    cudaStreamCreateWithFlags(&s1, cudaStreamNonBlocking);
    cudaStreamCreateWithFlags(&s2, cudaStreamNonBlocking);
    cudaStreamCreateWithFlags(&s3, cudaStreamNonBlocking);
    cudaStreamCreateWithFlags(&s4, cudaStreamNonBlocking);
    cudaEvent_t eFork, e1, e2, e3, e4;
    cudaEventCreateWithFlags(&eFork, cudaEventDisableTiming);
    cudaEventCreateWithFlags(&e1, cudaEventDisableTiming);
    cudaEventCreateWithFlags(&e2, cudaEventDisableTiming);
    cudaEventCreateWithFlags(&e3, cudaEventDisableTiming);
    cudaEventCreateWithFlags(&e4, cudaEventDisableTiming);

    cudaEventRecord(eFork, 0);
    cudaStreamWaitEvent(s1, eFork, 0);
    cudaStreamWaitEvent(s2, eFork, 0);
    cudaStreamWaitEvent(s3, eFork, 0);
    cudaStreamWaitEvent(s4, eFork, 0);

    // branch 3 (s3): CSR build
    zero_int_kernel<<<(Nn + 255) / 256, 256, 0, s3>>>(cnt, Nn);
    count_kernel<<<(Ee + 255) / 256, 256, 0, s3>>>(edge_index, cnt);
    scan_partial_kernel<<<SCAN_BLOCKS, 256, 0, s3>>>(cnt, partial);
    scan_base_kernel<<<1, 32, 0, s3>>>(partial, basep, off);
    scan_final_kernel<<<SCAN_BLOCKS, SCAN_CHUNK, 0, s3>>>(cnt, basep, off, cur);
    scatter_kernel<<<(Ee + 255) / 256, 256, 0, s3>>>(edge_index, cur, srcs, eids);
    cudaEventRecord(e3, s3);

    // branch 1 (s1): weight packs only
    {
        int n1 = LAYERS * 65536 + LAYERS * 320 * 64;
        pack_stage1<<<(n1 + 255) / 256, 256, 0, s1>>>(Wq, bq, Wk, bk, Wv, bv, We, Wskip,
                                                      Bp, biasp, Bc);
        int n2 = LAYERS * 65536 + LAYERS * 20480;
        pack_stage2<<<(n2 + 255) / 256, 256, 0, s1>>>(Bp, Bc, BfQ, BfC);
    }
    cudaEventRecord(e1, s1);

    // branch 4 (s4): node projection (independent of packs)
    pack_frag<<<(128 * 64 + 255) / 256, 256, 0, s4>>>(node_W, BfH, 128, 64);
    gemm_h_mma<<<(Nn + 127) / 128, 256, 0, s4>>>(x, BfH, node_b, h0, Nn, NODE_DIM, NODE_DIM);
    cudaEventRecord(e4, s4);

    // branch 2 (s2): edge MLP, then reorder into CSR order (needs CSR too)
    pack_frag<<<(64 * 64 + 255) / 256, 256, 0, s2>>>(e2_W, BfE, 64, 64);
    edge_mlp_mma<<<Ee / 128, 256, 0, s2>>>(edgeattr, e1_W, e1_b, BfE, e2_b, eb);
    cudaStreamWaitEvent(s2, e3, 0);
    reorder_e_kernel<<<(Ee * 8 + 255) / 256, 256, 0, s2>>>(eb, eids, ebp);
    cudaEventRecord(e2, s2);

    // stream 0: qkvqe l0 needs packs (s1) + h0 (s4)
    cudaStreamWaitEvent(0, e1, 0);
    cudaStreamWaitEvent(0, e4, 0);

    float* hc = h0;
    float* hn = h1;
    for (int l = 0; l < LAYERS; l++) {
        gemm_qkvqe_mma<<<dim3((Nn + 127) / 128, 4), 256>>>(hc, BfQ + l * 65536,
                                                           biasp + l * 1024, qf, qef, kvb);
        if (l == 0) {  // attn additionally needs ebp (s2, which includes CSR)
            cudaStreamWaitEvent(0, e2, 0);
        }
        attn_kernel<<<(Nn * 32 + 255) / 256, 256>>>(qf, qef, kvb, ebp, off, srcs, t, amean);
        conv_ln_mma<<<(Nn + 127) / 128, 256>>>(t, hc, BfC + l * 20480, bskip + l * 64,
                                               amean, ln_g + l * 64, ln_b + l * 64, hn);
        float* tmp = hc; hc = hn; hn = tmp;
    }
    pool_kernel<<<GRAPHS, HID>>>(hc, batch, cls_W, cls_b, out);

    cudaStreamDestroy(s1);
    cudaStreamDestroy(s2);
    cudaStreamDestroy(s3);
    cudaStreamDestroy(s4);
    cudaEventDestroy(eFork);
    cudaEventDestroy(e1);
    cudaEventDestroy(e2);
    cudaEventDestroy(e3);
    cudaEventDestroy(e4);
}

// round 15
// speedup vs baseline: 1.0711x; 1.0248x over previous
#include <cuda_runtime.h>
#include <cuda_bf16.h>
#include <math.h>

#define Nn 20000
#define Ee 256000
#define NODE_DIM 128
#define EDGE_DIM 8
#define HID 64
#define HEADS 4
#define HC 256
#define LAYERS 3
#define CLASSES 3
#define GRAPHS 64
#define SCAN_CHUNK 1024
#define SCAN_BLOCKS ((Nn + SCAN_CHUNK - 1) / SCAN_CHUNK)

// ---------------- scratch (static device allocations; no cudaMalloc) -------
__device__ float d_h0[Nn * HID];
__device__ float d_h1[Nn * HID];
__device__ __nv_bfloat16 d_qq[Nn * 512];          // interleaved [q(256) | qe(256)]
__device__ __nv_bfloat16 d_kvb[Nn * 512];         // interleaved [k(256) | v(256)]
__device__ __nv_bfloat16 d_eb[Ee * HID];
__device__ __nv_bfloat16 d_ebp[Ee * HID];         // eb permuted to CSR order
__device__ __nv_bfloat16 d_t[Nn * HC];            // bf16 attention outputs
__device__ __nv_bfloat16 d_amean[Nn * HID];
__device__ float d_Bp[LAYERS * HID * 1024];
__device__ float d_biasp[LAYERS * 1024];
__device__ float d_Bc[LAYERS * 320 * HID];
__device__ unsigned d_BfQ[LAYERS * HID * 1024];   // tf32 frag-order qkvqe B
__device__ unsigned d_BfC[LAYERS * 320 * HID];    // tf32 frag-order conv B
__device__ unsigned d_BfH[NODE_DIM * HID];        // tf32 frag-order node_W
__device__ unsigned d_BfE[HID * HID];             // tf32 frag-order e2_W
__device__ int d_cnt[Nn];
__device__ int d_off[Nn + 1];
__device__ int d_cur[Nn];
__device__ int d_partial[SCAN_BLOCKS];
__device__ int d_base[SCAN_BLOCKS];
__device__ int d_srcs[Ee];
__device__ int d_eids[Ee];

// ---------------- tf32 / mma helpers ---------------------------------------
__device__ __forceinline__ unsigned f2tf(float f) {
    unsigned u;
    asm("cvt.rna.tf32.f32 %0, %1;" : "=r"(u) : "f"(f));
    return u;
}

__device__ __forceinline__ void mma8(float c[4], unsigned a0, unsigned a1, unsigned a2,
                                     unsigned a3, unsigned b0, unsigned b1) {
    asm volatile(
        "mma.sync.aligned.m16n8k8.row.col.f32.tf32.tf32.f32 "
        "{%0,%1,%2,%3}, {%4,%5,%6,%7}, {%8,%9}, {%0,%1,%2,%3};"
        : "+f"(c[0]), "+f"(c[1]), "+f"(c[2]), "+f"(c[3])
        : "r"(a0), "r"(a1), "r"(a2), "r"(a3), "r"(b0), "r"(b1));
}

// stage 128x32 fp32 -> tf32 smem tile (pad 36 => conflict-free frag LDS)
__device__ __forceinline__ void stage_A(const float* __restrict__ A, int lda, int bm, int M,
                                        int k0, unsigned (*As)[36], int tid) {
    int ar = tid >> 1, ac = (tid & 1) * 16;
    int row = bm + ar;
    const float* Ap = A + (size_t)row * lda + k0 + ac;
    bool ok = row < M;
#pragma unroll
    for (int j = 0; j < 4; j++) {
        float4 v = ok ? *(const float4*)(Ap + 4 * j) : make_float4(0.f, 0.f, 0.f, 0.f);
        As[ar][ac + 4 * j + 0] = f2tf(v.x);
        As[ar][ac + 4 * j + 1] = f2tf(v.y);
        As[ar][ac + 4 * j + 2] = f2tf(v.z);
        As[ar][ac + 4 * j + 3] = f2tf(v.w);
    }
}

// stage 128x32 bf16 -> tf32 smem tile
__device__ __forceinline__ void stage_Abf(const __nv_bfloat16* __restrict__ A, int lda, int bm,
                                          int M, int k0, unsigned (*As)[36], int tid) {
    int ar = tid >> 1, ac = (tid & 1) * 16;
    int row = bm + ar;
    const __nv_bfloat16* Ap = A + (size_t)row * lda + k0 + ac;
    bool ok = row < M;
    uint4 z = make_uint4(0, 0, 0, 0);
    uint4 r0 = ok ? *(const uint4*)Ap : z;
    uint4 r1 = ok ? *(const uint4*)(Ap + 8) : z;
    const __nv_bfloat162* p0 = (const __nv_bfloat162*)&r0;
    const __nv_bfloat162* p1 = (const __nv_bfloat162*)&r1;
#pragma unroll
    for (int j = 0; j < 4; j++) {
        float2 f0 = __bfloat1622float2(p0[j]);
        float2 f1 = __bfloat1622float2(p1[j]);
        As[ar][ac + 2 * j + 0] = f2tf(f0.x);
        As[ar][ac + 2 * j + 1] = f2tf(f0.y);
        As[ar][ac + 8 + 2 * j + 0] = f2tf(f1.x);
        As[ar][ac + 8 + 2 * j + 1] = f2tf(f1.y);
    }
}

// one 32-wide K chunk: 4 k-steps of m16n8k8 across warp's 32x32 tile
__device__ __forceinline__ void mma_stage(const unsigned (*As)[36], const uint2* __restrict__ bst,
                                          float acc[2][4][4], int wm, int wn, int g, int tg,
                                          int lane) {
#pragma unroll
    for (int s = 0; s < 4; s++) {
        unsigned a[2][4];
#pragma unroll
        for (int t = 0; t < 2; t++) {
            int r = wm * 32 + t * 16 + g;
            a[t][0] = As[r][s * 8 + tg];
            a[t][1] = As[r + 8][s * 8 + tg];
            a[t][2] = As[r][s * 8 + tg + 4];
            a[t][3] = As[r + 8][s * 8 + tg + 4];
        }
        const uint2* bp = bst + ((s * 2 + wn) * 4) * 32 + lane;
#pragma unroll
        for (int u = 0; u < 4; u++) {
            uint2 b = bp[u * 32];
#pragma unroll
            for (int t = 0; t < 2; t++)
                mma8(acc[t][u], a[t][0], a[t][1], a[t][2], a[t][3], b.x, b.y);
        }
    }
}

// ---------------- CSR build -------------------------------------------------
__global__ void zero_int_kernel(int* p, int n) {
    int i = blockIdx.x * blockDim.x + threadIdx.x;
    if (i < n) p[i] = 0;
}

__global__ void count_kernel(const int* __restrict__ edge_index, int* __restrict__ cnt) {
    int i = blockIdx.x * blockDim.x + threadIdx.x;
    if (i < Ee) atomicAdd(&cnt[edge_index[Ee + i]], 1);
}

__global__ void scan_partial_kernel(const int* __restrict__ cnt, int* __restrict__ partial) {
    __shared__ int sh[256];
    int b = blockIdx.x, tid = threadIdx.x;
    int base = b * SCAN_CHUNK;
    int s = 0;
#pragma unroll
    for (int j = 0; j < SCAN_CHUNK / 256; j++) {
        int i = base + j * 256 + tid;
        s += (i < Nn) ? cnt[i] : 0;
    }
    sh[tid] = s;
    __syncthreads();
    for (int st = 128; st >= 1; st >>= 1) {
        if (tid < st) sh[tid] += sh[tid + st];
        __syncthreads();
    }
    if (tid == 0) partial[b] = sh[0];
}

__global__ void scan_base_kernel(const int* __restrict__ partial, int* __restrict__ base,
                                 int* __restrict__ off) {
    if (threadIdx.x == 0) {
        int run = 0;
        for (int i = 0; i < SCAN_BLOCKS; i++) { base[i] = run; run += partial[i]; }
        off[Nn] = run;
    }
}

__global__ void scan_final_kernel(const int* __restrict__ cnt, const int* __restrict__ base,
                                  int* __restrict__ off, int* __restrict__ cur) {
    __shared__ int sh[SCAN_CHUNK];
    int b = blockIdx.x, tid = threadIdx.x;
    int i = b * SCAN_CHUNK + tid;
    int v = (i < Nn) ? cnt[i] : 0;
    sh[tid] = v;
    __syncthreads();
    for (int s = 1; s < SCAN_CHUNK; s <<= 1) {
        int t2 = (tid >= s) ? sh[tid - s] : 0;
        __syncthreads();
        sh[tid] += t2;
        __syncthreads();
    }
    if (i < Nn) {
        int excl = sh[tid] - v + base[b];
        off[i] = excl;
        cur[i] = excl;
    }
}

__global__ void scatter_kernel(const int* __restrict__ edge_index, int* __restrict__ cur,
                               int* __restrict__ srcs, int* __restrict__ eids) {
    int i = blockIdx.x * blockDim.x + threadIdx.x;
    if (i < Ee) {
        int src = edge_index[i];
        int dst = edge_index[Ee + i];
        int pos = atomicAdd(&cur[dst], 1);
        srcs[pos] = src;
        eids[pos] = i;
    }
}

// permute eb into CSR order: ebp[i] = eb[eids[i]]
__global__ void reorder_e_kernel(const __nv_bfloat16* __restrict__ eb,
                                 const int* __restrict__ eids,
                                 __nv_bfloat16* __restrict__ ebp) {
    int idx = blockIdx.x * blockDim.x + threadIdx.x;
    if (idx >= Ee * 8) return;
    int i = idx >> 3;
    int c = (idx & 7) * 8;
    int eid = eids[i];
    *(uint4*)(ebp + (size_t)i * 64 + c) = *(const uint4*)(eb + (size_t)eid * 64 + c);
}

// ---------------- weight packing (fused) -------------------------------------
__global__ void pack_stage1(const float* __restrict__ Wq, const float* __restrict__ bq,
                            const float* __restrict__ Wk, const float* __restrict__ bk,
                            const float* __restrict__ Wv, const float* __restrict__ bv,
                            const float* __restrict__ We, const float* __restrict__ Wskip,
                            float* __restrict__ Bp, float* __restrict__ biasp,
                            float* __restrict__ Bc) {
    int idx = blockIdx.x * blockDim.x + threadIdx.x;
    if (idx < LAYERS * 65536) {
        int l = idx >> 16;
        int rem = idx & 65535;
        int j = rem >> 10;
        int col = rem & 1023;
        const float* Wql = Wq + l * 16384;
        const float* Wkl = Wk + l * 16384;
        const float* Wvl = Wv + l * 16384;
        const float* Wel = We + l * 16384;
        float v;
        if (col < 256) v = Wql[j * 256 + col];
        else if (col < 512) v = Wkl[j * 256 + col - 256];
        else if (col < 768) v = Wvl[j * 256 + col - 512];
        else {
            int d2 = col - 768; int h = d2 >> 6; int d = d2 & 63;
            float s = 0.f;
            for (int c = 0; c < 64; c++)
                s += Wql[j * 256 + h * 64 + c] * Wel[d * 256 + h * 64 + c];
            v = s;
        }
        Bp[idx] = v;
        if (j == 0) {
            float bvv;
            if (col < 256) bvv = bq[l * 256 + col];
            else if (col < 512) bvv = bk[l * 256 + col - 256];
            else if (col < 768) bvv = bv[l * 256 + col - 512];
            else {
                int d2 = col - 768; int h = d2 >> 6; int d = d2 & 63;
                float s = 0.f;
                for (int c = 0; c < 64; c++)
                    s += bq[l * 256 + h * 64 + c] * Wel[d * 256 + h * 64 + c];
                bvv = s;
            }
            biasp[l * 1024 + col] = bvv;
        }
    } else {
        int j = idx - LAYERS * 65536;
        if (j >= LAYERS * 320 * 64) return;
        int l = j / (320 * 64);
        int r = (j >> 6) % 320;
        int c = j & 63;
        float v;
        if (r < 256) {
            int h = r >> 6, d = r & 63;
            v = We[l * 16384 + d * 256 + h * 64 + c];
        } else {
            v = Wskip[l * 4096 + (r - 256) * 64 + c];
        }
        Bc[j] = v;
    }
}

__device__ __forceinline__ void frag_pack(const float* __restrict__ B, unsigned* __restrict__ out,
                                          int idx, int K, int Ncols) {
    int ks_total = K >> 3;
    int p = idx & 1;
    int lane = (idx >> 1) & 31;
    int u = (idx >> 6) & 3;
    int wn = (idx >> 8) & 1;
    int rest = idx >> 9;
    int ks = rest % ks_total;
    int bnb = rest / ks_total;
    int k = ks * 8 + (lane & 3) + 4 * p;
    int n = bnb * 64 + wn * 32 + u * 8 + (lane >> 2);
    out[idx] = f2tf(B[k * Ncols + n]);
}

__global__ void pack_frag(const float* __restrict__ B, unsigned* __restrict__ out,
                          int K, int Ncols) {
    int idx = blockIdx.x * blockDim.x + threadIdx.x;
    if (idx < K * Ncols) frag_pack(B, out, idx, K, Ncols);
}

__global__ void pack_stage2(const float* __restrict__ Bp, const float* __restrict__ Bc,
                            unsigned* __restrict__ BfQ, unsigned* __restrict__ BfC) {
    int idx = blockIdx.x * blockDim.x + threadIdx.x;
    if (idx < LAYERS * 65536) {
        int l = idx >> 16;
        frag_pack(Bp + l * 65536, BfQ + l * 65536, idx & 65535, 64, 1024);
    } else {
        int j = idx - LAYERS * 65536;
        if (j >= LAYERS * 20480) return;
        int l = j / 20480;
        frag_pack(Bc + l * 20480, BfC + l * 20480, j % 20480, 320, 64);
    }
}

// ---------------- node projection (tf32 MMA, double-buffered) ---------------
__global__ void gemm_h_mma(const float* __restrict__ A, const unsigned* __restrict__ Bf,
                           const float* __restrict__ bias, float* __restrict__ C,
                           int M, int K, int lda) {
    __shared__ unsigned As[2][128][36];
    float acc[2][4][4] = {};
    int bm = blockIdx.x * 128;
    int tid = threadIdx.x, w = tid >> 5, lane = tid & 31;
    int wm = w & 3, wn = w >> 2, g = lane >> 2, tg = lane & 3;
    int nst = K >> 5;
    stage_A(A, lda, bm, M, 0, As[0], tid);
    __syncthreads();
    for (int st = 0; st < nst; st++) {
        int cb = st & 1;
        if (st + 1 < nst) stage_A(A, lda, bm, M, (st + 1) * 32, As[cb ^ 1], tid);
        mma_stage(As[cb], (const uint2*)Bf + st * 1024, acc, wm, wn, g, tg, lane);
        __syncthreads();
    }
#pragma unroll
    for (int u = 0; u < 4; u++) {
        int col = wn * 32 + u * 8 + 2 * tg;
        float2 bb = *(const float2*)(bias + col);
#pragma unroll
        for (int t = 0; t < 2; t++) {
            int row = bm + wm * 32 + t * 16 + g;
            if (row < M) {
                float2 o = {acc[t][u][0] + bb.x, acc[t][u][1] + bb.y};
                *(float2*)(C + (size_t)row * 64 + col) = o;
            }
            if (row + 8 < M) {
                float2 o = {acc[t][u][2] + bb.x, acc[t][u][3] + bb.y};
                *(float2*)(C + (size_t)(row + 8) * 64 + col) = o;
            }
        }
    }
}

// ---------------- fused QKVQE (tf32 MMA): A staged once per 4 n-blocks ------
// gridDim.y = 4; bn = 4*blockIdx.y + {0..3}; j-loop NOT unrolled (reg reuse).
// All outputs bf16: q/qe interleaved in qq, k/v interleaved in kvb.
__global__ void __launch_bounds__(256)
gemm_qkvqe_mma(const float* __restrict__ h, const unsigned* __restrict__ BfQ,
               const float* __restrict__ biasp,
               __nv_bfloat16* __restrict__ qq, __nv_bfloat16* __restrict__ kvb) {
    __shared__ unsigned As[2][128][36];
    int bm = blockIdx.x * 128;
    int tid = threadIdx.x, w = tid >> 5, lane = tid & 31;
    int wm = w & 3, wn = w >> 2, g = lane >> 2, tg = lane & 3;
    stage_A(h, 64, bm, Nn, 0, As[0], tid);
    stage_A(h, 64, bm, Nn, 32, As[1], tid);
    __syncthreads();
#pragma unroll 1
    for (int j = 0; j < 4; j++) {
        int bn = blockIdx.y * 4 + j;
        const uint2* Bfb = (const uint2*)BfQ + bn * 2048;
        float acc[2][4][4] = {};
        mma_stage(As[0], Bfb, acc, wm, wn, g, tg, lane);
        mma_stage(As[1], Bfb + 1024, acc, wm, wn, g, tg, lane);
        int sec = bn >> 2;
        __nv_bfloat16* dstbase = (sec == 0) ? qq
                               : (sec == 3) ? qq + 256
                               : (sec == 1) ? kvb
                                            : kvb + 256;
#pragma unroll
        for (int u = 0; u < 4; u++) {
            int colL = wn * 32 + u * 8 + 2 * tg;
            float2 bb = *(const float2*)(biasp + bn * 64 + colL);
            int coff = (bn & 3) * 64 + colL;
#pragma unroll
            for (int t = 0; t < 2; t++) {
#pragma unroll
                for (int hh = 0; hh < 2; hh++) {
                    int row = bm + wm * 32 + t * 16 + g + 8 * hh;
                    if (row >= Nn) continue;
                    float v0 = acc[t][u][2 * hh + 0] + bb.x;
                    float v1 = acc[t][u][2 * hh + 1] + bb.y;
                    *(__nv_bfloat162*)(dstbase + (size_t)row * 512 + coff) =
                        __floats2bfloat162_rn(v0, v1);
                }
            }
        }
    }
}

// ---------------- fused conv (tf32 MMA, double-buffered) + LN + relu --------
__global__ void conv_ln_mma(const __nv_bfloat16* __restrict__ t, const float* __restrict__ hres,
                            const unsigned* __restrict__ BfC, const float* __restrict__ bskip,
                            const __nv_bfloat16* __restrict__ amean,
                            const float* __restrict__ gam,
                            const float* __restrict__ bet, float* __restrict__ hout) {
    __shared__ unsigned As[2][128][36];
    __shared__ float Ssum[128][2];
    __shared__ float Ssq[128][2];
    float acc[2][4][4] = {};
    int bm = blockIdx.x * 128;
    int tid = threadIdx.x, w = tid >> 5, lane = tid & 31;
    int wm = w & 3, wn = w >> 2, g = lane >> 2, tg = lane & 3;
    stage_Abf(t, 256, bm, Nn, 0, As[0], tid);
    __syncthreads();
    for (int st = 0; st < 10; st++) {
        int cb = st & 1;
        int nx = st + 1;
        if (nx < 8) stage_Abf(t, 256, bm, Nn, nx * 32, As[cb ^ 1], tid);
        else if (nx < 10) stage_A(hres, 64, bm, Nn, (nx - 8) * 32, As[cb ^ 1], tid);
        mma_stage(As[cb], (const uint2*)BfC + st * 1024, acc, wm, wn, g, tg, lane);
        __syncthreads();
    }
    float xs[2][4][4];
#pragma unroll
    for (int u = 0; u < 4; u++) {
        int col = wn * 32 + u * 8 + 2 * tg;
        float2 bb = *(const float2*)(bskip + col);
#pragma unroll
        for (int t2 = 0; t2 < 2; t2++) {
#pragma unroll
            for (int hh = 0; hh < 2; hh++) {
                int row = bm + wm * 32 + t2 * 16 + g + 8 * hh;
                float2 am = make_float2(0.f, 0.f), hr = make_float2(0.f, 0.f);
                if (row < Nn) {
                    am = __bfloat1622float2(
                        *(const __nv_bfloat162*)(amean + (size_t)row * 64 + col));
                    hr = *(const float2*)(hres + (size_t)row * 64 + col);
                }
                xs[t2][u][2 * hh + 0] = acc[t2][u][2 * hh + 0] + bb.x + am.x + hr.x;
                xs[t2][u][2 * hh + 1] = acc[t2][u][2 * hh + 1] + bb.y + am.y + hr.y;
            }
        }
    }
#pragma unroll
    for (int t2 = 0; t2 < 2; t2++) {
#pragma unroll
        for (int hh = 0; hh < 2; hh++) {
            float s = 0.f, q = 0.f;
#pragma unroll
            for (int u = 0; u < 4; u++) {
                float a = xs[t2][u][2 * hh + 0], b = xs[t2][u][2 * hh + 1];
                s += a + b;
                q += a * a + b * b;
            }
            s += __shfl_xor_sync(0xffffffffu, s, 1);
            s += __shfl_xor_sync(0xffffffffu, s, 2);
            q += __shfl_xor_sync(0xffffffffu, q, 1);
            q += __shfl_xor_sync(0xffffffffu, q, 2);
            if (tg == 0) {
                int lr = wm * 32 + t2 * 16 + g + 8 * hh;
                Ssum[lr][wn] = s;
                Ssq[lr][wn] = q;
            }
        }
    }
    __syncthreads();
#pragma unroll
    for (int t2 = 0; t2 < 2; t2++) {
#pragma unroll
        for (int hh = 0; hh < 2; hh++) {
            int lr = wm * 32 + t2 * 16 + g + 8 * hh;
            int row = bm + lr;
            float m = (Ssum[lr][0] + Ssum[lr][1]) * (1.f / 64.f);
            float var = (Ssq[lr][0] + Ssq[lr][1]) * (1.f / 64.f) - m * m;
            float rs = rsqrtf(var + 1e-5f);
            if (row >= Nn) continue;
#pragma unroll
            for (int u = 0; u < 4; u++) {
                int col = wn * 32 + u * 8 + 2 * tg;
                float2 gg = *(const float2*)(gam + col);
                float2 b2 = *(const float2*)(bet + col);
                float2 o;
                o.x = fmaxf((xs[t2][u][2 * hh + 0] - m) * rs * gg.x + b2.x, 0.f);
                o.y = fmaxf((xs[t2][u][2 * hh + 1] - m) * rs * gg.y + b2.y, 0.f);
                *(float2*)(hout + (size_t)row * 64 + col) = o;
            }
        }
    }
}

// ---------------- fused edge MLP (tf32 MMA): eb = bf16(relu(ea@W1+b1)@W2+b2)
__global__ void edge_mlp_mma(const float* __restrict__ ea, const float* __restrict__ W1,
                             const float* __restrict__ b1, const unsigned* __restrict__ BfE,
                             const float* __restrict__ b2, __nv_bfloat16* __restrict__ eb) {
    __shared__ unsigned As[128][68];
    __shared__ float W1s[EDGE_DIM * HID];
    __shared__ float b1s[HID];
    int tid = threadIdx.x, w = tid >> 5, lane = tid & 31;
    int wm = w & 3, wn = w >> 2, g = lane >> 2, tg = lane & 3;
    int be = blockIdx.x * 128;
    for (int i = tid; i < EDGE_DIM * HID; i += 256) W1s[i] = W1[i];
    if (tid < HID) b1s[tid] = b1[tid];
    __syncthreads();
    {
        int r = tid >> 1, half = tid & 1;
        float av[EDGE_DIM];
        const float* eap = ea + (size_t)(be + r) * EDGE_DIM;
#pragma unroll
        for (int d = 0; d < EDGE_DIM; d++) av[d] = eap[d];
#pragma unroll
        for (int c = 0; c < 32; c++) {
            int col = half * 32 + c;
            float s = b1s[col];
#pragma unroll
            for (int d = 0; d < EDGE_DIM; d++) s += av[d] * W1s[d * HID + col];
            As[r][col] = f2tf(fmaxf(s, 0.f));
        }
    }
    __syncthreads();
    float acc[2][4][4] = {};
#pragma unroll
    for (int st = 0; st < 2; st++) {
#pragma unroll
        for (int s = 0; s < 4; s++) {
            unsigned a[2][4];
#pragma unroll
            for (int t = 0; t < 2; t++) {
                int r = wm * 32 + t * 16 + g;
                a[t][0] = As[r][st * 32 + s * 8 + tg];
                a[t][1] = As[r + 8][st * 32 + s * 8 + tg];
                a[t][2] = As[r][st * 32 + s * 8 + tg + 4];
                a[t][3] = As[r + 8][st * 32 + s * 8 + tg + 4];
            }
            const uint2* bp = (const uint2*)BfE + st * 1024 + ((s * 2 + wn) * 4) * 32 + lane;
#pragma unroll
            for (int u = 0; u < 4; u++) {
                uint2 b = bp[u * 32];
#pragma unroll
                for (int t = 0; t < 2; t++)
                    mma8(acc[t][u], a[t][0], a[t][1], a[t][2], a[t][3], b.x, b.y);
            }
        }
    }
#pragma unroll
    for (int u = 0; u < 4; u++) {
        int col = wn * 32 + u * 8 + 2 * tg;
        float2 bb = *(const float2*)(b2 + col);
#pragma unroll
        for (int t = 0; t < 2; t++) {
#pragma unroll
            for (int hh = 0; hh < 2; hh++) {
                int row = be + wm * 32 + t * 16 + g + 8 * hh;
                float v0 = acc[t][u][2 * hh + 0] + bb.x;
                float v1 = acc[t][u][2 * hh + 1] + bb.y;
                *(__nv_bfloat162*)(eb + (size_t)row * HID + col) = __floats2bfloat162_rn(v0, v1);
            }
        }
    }
}

// ---------------- per-node attention: bf16 q/qe, raw bf16 gathers -----------
__device__ __forceinline__ float dotqk(const float* qv, const float* qev, uint4 kr, uint4 er) {
    const __nv_bfloat162* kp = (const __nv_bfloat162*)&kr;
    const __nv_bfloat162* ep = (const __nv_bfloat162*)&er;
    float p = 0.f;
#pragma unroll
    for (int t = 0; t < 4; t++) {
        float2 kf = __bfloat1622float2(kp[t]);
        float2 ef = __bfloat1622float2(ep[t]);
        p += qv[2 * t] * kf.x + qv[2 * t + 1] * kf.y;
        p += qev[2 * t] * ef.x + qev[2 * t + 1] * ef.y;
    }
    return p;
}

__device__ __forceinline__ void aggr(float* acc, float* tac, float wgt, uint4 vr, uint4 er) {
    const __nv_bfloat162* vp = (const __nv_bfloat162*)&vr;
    const __nv_bfloat162* ep = (const __nv_bfloat162*)&er;
#pragma unroll
    for (int t = 0; t < 4; t++) {
        float2 vf = __bfloat1622float2(vp[t]);
        float2 ef = __bfloat1622float2(ep[t]);
        acc[2 * t + 0] += wgt * vf.x;
        acc[2 * t + 1] += wgt * vf.y;
        tac[2 * t + 0] += wgt * ef.x;
        tac[2 * t + 1] += wgt * ef.y;
    }
}

__global__ void __launch_bounds__(256, 4)
attn_kernel(const __nv_bfloat16* __restrict__ qq,
            const __nv_bfloat16* __restrict__ kvb, const __nv_bfloat16* __restrict__ ebp,
            const int* __restrict__ off, const int* __restrict__ srcs,
            __nv_bfloat16* __restrict__ t_out, __nv_bfloat16* __restrict__ amean) {
    int warp = (blockIdx.x * blockDim.x + threadIdx.x) >> 5;
    if (warp >= Nn) return;
    int lane = threadIdx.x & 31;
    int g = lane >> 3;
    int li = lane & 7;
    int n = warp;
    int base = n * HC + g * 64 + li * 8;
    int hoff = g * 64 + li * 8;
    float qv[8], qev[8];
    {
        // bf16 q/qe load; fold softmax scale (1/8, exact pow2) into conversion
        uint4 qr = *(const uint4*)(qq + (size_t)n * 512 + hoff);
        uint4 qer = *(const uint4*)(qq + (size_t)n * 512 + 256 + hoff);
        const __nv_bfloat162* qp = (const __nv_bfloat162*)&qr;
        const __nv_bfloat162* qep = (const __nv_bfloat162*)&qer;
#pragma unroll
        for (int t = 0; t < 4; t++) {
            float2 f0 = __bfloat1622float2(qp[t]);
            float2 f1 = __bfloat1622float2(qep[t]);
            qv[2 * t] = f0.x * 0.125f; qv[2 * t + 1] = f0.y * 0.125f;
            qev[2 * t] = f1.x * 0.125f; qev[2 * t + 1] = f1.y * 0.125f;
        }
    }

    int s0 = off[n], s1 = off[n + 1];
    float denom = 0.f;
    float acc[8] = {}, tac[8] = {};

    int i = s0;
    for (; i + 2 <= s1; i += 2) {
        int n0 = srcs[i];
        int n1 = srcs[i + 1];
        uint4 k0 = *(const uint4*)(kvb + (size_t)n0 * 512 + hoff);
        uint4 k1 = *(const uint4*)(kvb + (size_t)n1 * 512 + hoff);
        uint4 v0 = *(const uint4*)(kvb + (size_t)n0 * 512 + 256 + hoff);
        uint4 v1 = *(const uint4*)(kvb + (size_t)n1 * 512 + 256 + hoff);
        uint4 e0 = *(const uint4*)(ebp + (size_t)i * 64 + li * 8);
        uint4 e1 = *(const uint4*)(ebp + (size_t)(i + 1) * 64 + li * 8);
        float p0 = dotqk(qv, qev, k0, e0);
        float p1 = dotqk(qv, qev, k1, e1);
        p0 += __shfl_xor_sync(0xffffffffu, p0, 1);
        p1 += __shfl_xor_sync(0xffffffffu, p1, 1);
        p0 += __shfl_xor_sync(0xffffffffu, p0, 2);
        p1 += __shfl_xor_sync(0xffffffffu, p1, 2);
        p0 += __shfl_xor_sync(0xffffffffu, p0, 4);
        p1 += __shfl_xor_sync(0xffffffffu, p1, 4);
        float w0 = __expf(p0);
        float w1 = __expf(p1);
        denom += w0 + w1;
        aggr(acc, tac, w0, v0, e0);
        aggr(acc, tac, w1, v1, e1);
    }
    if (i < s1) {
        int n0 = srcs[i];
        uint4 k0 = *(const uint4*)(kvb + (size_t)n0 * 512 + hoff);
        uint4 v0 = *(const uint4*)(kvb + (size_t)n0 * 512 + 256 + hoff);
        uint4 e0 = *(const uint4*)(ebp + (size_t)i * 64 + li * 8);
        float p0 = dotqk(qv, qev, k0, e0);
        p0 += __shfl_xor_sync(0xffffffffu, p0, 1);
        p0 += __shfl_xor_sync(0xffffffffu, p0, 2);
        p0 += __shfl_xor_sync(0xffffffffu, p0, 4);
        float w0 = __expf(p0);
        denom += w0;
        aggr(acc, tac, w0, v0, e0);
    }
    float inv = (denom > 0.f) ? 1.f / denom : 0.f;
    float qinv = 0.25f * inv;
    {
        uint4 to;
        __nv_bfloat162* top = (__nv_bfloat162*)&to;
#pragma unroll
        for (int t = 0; t < 4; t++)
            top[t] = __floats2bfloat162_rn(tac[2 * t] * qinv, tac[2 * t + 1] * qinv);
        *(uint4*)(t_out + base) = to;
    }
    float red[8];
#pragma unroll
    for (int j = 0; j < 8; j++) {
        float s = acc[j] * inv;
        s += __shfl_xor_sync(0xffffffffu, s, 8);
        s += __shfl_xor_sync(0xffffffffu, s, 16);
        red[j] = 0.25f * s;
    }
    if (g == 0) {
        uint4 ao;
        __nv_bfloat162* aop = (__nv_bfloat162*)&ao;
#pragma unroll
        for (int t = 0; t < 4; t++)
            aop[t] = __floats2bfloat162_rn(red[2 * t], red[2 * t + 1]);
        *(uint4*)(amean + (size_t)n * 64 + li * 8) = ao;
    }
}

// ---------------- mean-pool + classifier + log_softmax ----------------------
__global__ void pool_kernel(const float* __restrict__ h, const int* __restrict__ batch,
                            const float* __restrict__ clsW, const float* __restrict__ clsb,
                            float* __restrict__ out) {
    int gid = blockIdx.x;
    int c = threadIdx.x;
    int lo = 0, hi = Nn;
    while (lo < hi) { int mid = (lo + hi) >> 1; if (batch[mid] < gid) lo = mid + 1; else hi = mid; }
    int start = lo;
    lo = start; hi = Nn;
    while (lo < hi) { int mid = (lo + hi) >> 1; if (batch[mid] < gid + 1) lo = mid + 1; else hi = mid; }
    int end = lo;
    float acc = 0.f;
    for (int r = start; r < end; r++) acc += h[r * HID + c];
    int cntn = end - start;
    float pooled = acc / fmaxf((float)cntn, 1.f);
    __shared__ float ps[HID];
    __shared__ float lg[CLASSES];
    ps[c] = pooled;
    __syncthreads();
    if (c < CLASSES) {
        float s = clsb[c];
        for (int d = 0; d < HID; d++) s += ps[d] * clsW[d * CLASSES + c];
        lg[c] = s;
    }
    __syncthreads();
    if (c == 0) {
        float mm = fmaxf(lg[0], fmaxf(lg[1], lg[2]));
        float se = expf(lg[0] - mm) + expf(lg[1] - mm) + expf(lg[2] - mm);
        float lse = mm + logf(se);
        out[gid * CLASSES + 0] = lg[0] - lse;
        out[gid * CLASSES + 1] = lg[1] - lse;
        out[gid * CLASSES + 2] = lg[2] - lse;
    }
}

// ---------------- host launcher --------------------------------------------
extern "C" void kernel_launch(void* const* d_in, const int* in_sizes, int n_in,
                              void* d_out, int out_size) {
    (void)in_sizes; (void)n_in; (void)out_size;
    const float* x        = (const float*)d_in[0];
    const float* edgeattr = (const float*)d_in[1];
    const float* node_W   = (const float*)d_in[2];
    const float* node_b   = (const float*)d_in[3];
    const float* e1_W     = (const float*)d_in[4];
    const float* e1_b     = (const float*)d_in[5];
    const float* e2_W     = (const float*)d_in[6];
    const float* e2_b     = (const float*)d_in[7];
    const float* Wq       = (const float*)d_in[8];
    const float* bq       = (const float*)d_in[9];
    const float* Wk       = (const float*)d_in[10];
    const float* bk       = (const float*)d_in[11];
    const float* Wv       = (const float*)d_in[12];
    const float* bv       = (const float*)d_in[13];
    const float* We       = (const float*)d_in[14];
    const float* Wskip    = (const float*)d_in[15];
    const float* bskip    = (const float*)d_in[16];
    const float* ln_g     = (const float*)d_in[17];
    const float* ln_b     = (const float*)d_in[18];
    const float* cls_W    = (const float*)d_in[19];
    const float* cls_b    = (const float*)d_in[20];
    const int* edge_index = (const int*)d_in[21];
    const int* batch      = (const int*)d_in[22];
    float* out            = (float*)d_out;

    float *h0, *h1, *Bp, *biasp, *Bc;
    unsigned *BfQ, *BfC, *BfH, *BfE;
    __nv_bfloat16 *qq, *kvb, *eb, *ebp, *t, *amean;
    int *cnt, *off, *cur, *partial, *basep, *srcs, *eids;
    cudaGetSymbolAddress((void**)&h0, d_h0);
    cudaGetSymbolAddress((void**)&h1, d_h1);
    cudaGetSymbolAddress((void**)&qq, d_qq);
    cudaGetSymbolAddress((void**)&kvb, d_kvb);
    cudaGetSymbolAddress((void**)&eb, d_eb);
    cudaGetSymbolAddress((void**)&ebp, d_ebp);
    cudaGetSymbolAddress((void**)&t, d_t);
    cudaGetSymbolAddress((void**)&amean, d_amean);
    cudaGetSymbolAddress((void**)&Bp, d_Bp);
    cudaGetSymbolAddress((void**)&biasp, d_biasp);
    cudaGetSymbolAddress((void**)&Bc, d_Bc);
    cudaGetSymbolAddress((void**)&BfQ, d_BfQ);
    cudaGetSymbolAddress((void**)&BfC, d_BfC);
    cudaGetSymbolAddress((void**)&BfH, d_BfH);
    cudaGetSymbolAddress((void**)&BfE, d_BfE);
    cudaGetSymbolAddress((void**)&cnt, d_cnt);
    cudaGetSymbolAddress((void**)&off, d_off);
    cudaGetSymbolAddress((void**)&cur, d_cur);
    cudaGetSymbolAddress((void**)&partial, d_partial);
    cudaGetSymbolAddress((void**)&basep, d_base);
    cudaGetSymbolAddress((void**)&srcs, d_srcs);
    cudaGetSymbolAddress((void**)&eids, d_eids);

    // ---- multi-stream prologue: CSR (s3), packs (s1), gemm_h (s4), edge MLP (s2)
    cudaStream_t s1, s2, s3, s4;
    cudaStreamCreateWithFlags(&s1, cudaStreamNonBlocking);
    cudaStreamCreateWithFlags(&s2, cudaStreamNonBlocking);
    cudaStreamCreateWithFlags(&s3, cudaStreamNonBlocking);
    cudaStreamCreateWithFlags(&s4, cudaStreamNonBlocking);
    cudaEvent_t eFork, e1, e2, e3, e4;
    cudaEventCreateWithFlags(&eFork, cudaEventDisableTiming);
    cudaEventCreateWithFlags(&e1, cudaEventDisableTiming);
    cudaEventCreateWithFlags(&e2, cudaEventDisableTiming);
    cudaEventCreateWithFlags(&e3, cudaEventDisableTiming);
    cudaEventCreateWithFlags(&e4, cudaEventDisableTiming);

    cudaEventRecord(eFork, 0);
    cudaStreamWaitEvent(s1, eFork, 0);
    cudaStreamWaitEvent(s2, eFork, 0);
    cudaStreamWaitEvent(s3, eFork, 0);
    cudaStreamWaitEvent(s4, eFork, 0);

    // branch 3 (s3): CSR build
    zero_int_kernel<<<(Nn + 255) / 256, 256, 0, s3>>>(cnt, Nn);
    count_kernel<<<(Ee + 255) / 256, 256, 0, s3>>>(edge_index, cnt);
    scan_partial_kernel<<<SCAN_BLOCKS, 256, 0, s3>>>(cnt, partial);
    scan_base_kernel<<<1, 32, 0, s3>>>(partial, basep, off);
    scan_final_kernel<<<SCAN_BLOCKS, SCAN_CHUNK, 0, s3>>>(cnt, basep, off, cur);
    scatter_kernel<<<(Ee + 255) / 256, 256, 0, s3>>>(edge_index, cur, srcs, eids);
    cudaEventRecord(e3, s3);

    // branch 1 (s1): weight packs only
    {
        int n1 = LAYERS * 65536 + LAYERS * 320 * 64;
        pack_stage1<<<(n1 + 255) / 256, 256, 0, s1>>>(Wq, bq, Wk, bk, Wv, bv, We, Wskip,
                                                      Bp, biasp, Bc);
        int n2 = LAYERS * 65536 + LAYERS * 20480;
        pack_stage2<<<(n2 + 255) / 256, 256, 0, s1>>>(Bp, Bc, BfQ, BfC);
    }
    cudaEventRecord(e1, s1);

    // branch 4 (s4): node projection (independent of packs)
    pack_frag<<<(128 * 64 + 255) / 256, 256, 0, s4>>>(node_W, BfH, 128, 64);
    gemm_h_mma<<<(Nn + 127) / 128, 256, 0, s4>>>(x, BfH, node_b, h0, Nn, NODE_DIM, NODE_DIM);
    cudaEventRecord(e4, s4);

    // branch 2 (s2): edge MLP, then reorder into CSR order (needs CSR too)
    pack_frag<<<(64 * 64 + 255) / 256, 256, 0, s2>>>(e2_W, BfE, 64, 64);
    edge_mlp_mma<<<Ee / 128, 256, 0, s2>>>(edgeattr, e1_W, e1_b, BfE, e2_b, eb);
    cudaStreamWaitEvent(s2, e3, 0);
    reorder_e_kernel<<<(Ee * 8 + 255) / 256, 256, 0, s2>>>(eb, eids, ebp);
    cudaEventRecord(e2, s2);

    // stream 0: qkvqe l0 needs packs (s1) + h0 (s4)
    cudaStreamWaitEvent(0, e1, 0);
    cudaStreamWaitEvent(0, e4, 0);

    float* hc = h0;
    float* hn = h1;
    for (int l = 0; l < LAYERS; l++) {
        gemm_qkvqe_mma<<<dim3((Nn + 127) / 128, 4), 256>>>(hc, BfQ + l * 65536,
                                                           biasp + l * 1024, qq, kvb);
        if (l == 0) {  // attn additionally needs ebp (s2, which includes CSR)
            cudaStreamWaitEvent(0, e2, 0);
        }
        attn_kernel<<<(Nn * 32 + 255) / 256, 256>>>(qq, kvb, ebp, off, srcs, t, amean);
        conv_ln_mma<<<(Nn + 127) / 128, 256>>>(t, hc, BfC + l * 20480, bskip + l * 64,
                                               amean, ln_g + l * 64, ln_b + l * 64, hn);
        float* tmp = hc; hc = hn; hn = tmp;
    }
    pool_kernel<<<GRAPHS, HID>>>(hc, batch, cls_W, cls_b, out);

    cudaStreamDestroy(s1);
    cudaStreamDestroy(s2);
    cudaStreamDestroy(s3);
    cudaStreamDestroy(s4);
    cudaEventDestroy(eFork);
    cudaEventDestroy(e1);
    cudaEventDestroy(e2);
    cudaEventDestroy(e3);
    cudaEventDestroy(e4);
}

// round 16
// speedup vs baseline: 1.1572x; 1.0804x over previous
#include <cuda_runtime.h>
#include <cuda_bf16.h>
#include <cuda_fp8.h>
#include <math.h>

#define Nn 20000
#define Ee 256000
#define NODE_DIM 128
#define EDGE_DIM 8
#define HID 64
#define HEADS 4
#define HC 256
#define LAYERS 3
#define CLASSES 3
#define GRAPHS 64
#define SCAN_CHUNK 1024
#define SCAN_BLOCKS ((Nn + SCAN_CHUNK - 1) / SCAN_CHUNK)

// ---------------- scratch (static device allocations; no cudaMalloc) -------
__device__ float d_h0[Nn * HID];
__device__ float d_h1[Nn * HID];
__device__ __nv_bfloat16 d_qq[Nn * 512];          // interleaved [q(256) | qe(256)] bf16
__device__ unsigned char d_kv8[Nn * 512];         // interleaved [k(256) | v(256)] fp8 e4m3
__device__ unsigned char d_eb8[Ee * 64];          // edge features fp8 (edge-id order)
__device__ unsigned char d_e8p[Ee * 64];          // fp8 edge features, CSR order
__device__ __nv_bfloat16 d_t[Nn * HC];            // bf16 attention outputs
__device__ __nv_bfloat16 d_amean[Nn * HID];
__device__ float d_Bp[LAYERS * HID * 1024];
__device__ float d_biasp[LAYERS * 1024];
__device__ float d_Bc[LAYERS * 320 * HID];
__device__ unsigned d_BfQ[LAYERS * HID * 1024];   // tf32 frag-order qkvqe B
__device__ unsigned d_BfC[LAYERS * 320 * HID];    // tf32 frag-order conv B
__device__ unsigned d_BfH[NODE_DIM * HID];        // tf32 frag-order node_W
__device__ unsigned d_BfE[HID * HID];             // tf32 frag-order e2_W
__device__ int d_cnt[Nn];
__device__ int d_off[Nn + 1];
__device__ int d_cur[Nn];
__device__ int d_partial[SCAN_BLOCKS];
__device__ int d_base[SCAN_BLOCKS];
__device__ int d_srcs[Ee];
__device__ int d_eids[Ee];

// ---------------- tf32 / mma / fp8 helpers ----------------------------------
__device__ __forceinline__ unsigned f2tf(float f) {
    unsigned u;
    asm("cvt.rna.tf32.f32 %0, %1;" : "=r"(u) : "f"(f));
    return u;
}

__device__ __forceinline__ unsigned short f2_to_fp8x2(float v0, float v1) {
    return __nv_cvt_float2_to_fp8x2(make_float2(v0, v1), __NV_SATFINITE, __NV_E4M3);
}

__device__ __forceinline__ float2 fp8x2_to_f2(unsigned short u) {
    __half2_raw hr = __nv_cvt_fp8x2_to_halfraw2(u, __NV_E4M3);
    return __half22float2(*reinterpret_cast<__half2*>(&hr));
}

__device__ __forceinline__ void mma8(float c[4], unsigned a0, unsigned a1, unsigned a2,
                                     unsigned a3, unsigned b0, unsigned b1) {
    asm volatile(
        "mma.sync.aligned.m16n8k8.row.col.f32.tf32.tf32.f32 "
        "{%0,%1,%2,%3}, {%4,%5,%6,%7}, {%8,%9}, {%0,%1,%2,%3};"
        : "+f"(c[0]), "+f"(c[1]), "+f"(c[2]), "+f"(c[3])
        : "r"(a0), "r"(a1), "r"(a2), "r"(a3), "r"(b0), "r"(b1));
}

// stage 128x32 fp32 -> tf32 smem tile (pad 36 => conflict-free frag LDS)
__device__ __forceinline__ void stage_A(const float* __restrict__ A, int lda, int bm, int M,
                                        int k0, unsigned (*As)[36], int tid) {
    int ar = tid >> 1, ac = (tid & 1) * 16;
    int row = bm + ar;
    const float* Ap = A + (size_t)row * lda + k0 + ac;
    bool ok = row < M;
#pragma unroll
    for (int j = 0; j < 4; j++) {
        float4 v = ok ? *(const float4*)(Ap + 4 * j) : make_float4(0.f, 0.f, 0.f, 0.f);
        As[ar][ac + 4 * j + 0] = f2tf(v.x);
        As[ar][ac + 4 * j + 1] = f2tf(v.y);
        As[ar][ac + 4 * j + 2] = f2tf(v.z);
        As[ar][ac + 4 * j + 3] = f2tf(v.w);
    }
}

// stage 128x32 bf16 -> tf32 smem tile
__device__ __forceinline__ void stage_Abf(const __nv_bfloat16* __restrict__ A, int lda, int bm,
                                          int M, int k0, unsigned (*As)[36], int tid) {
    int ar = tid >> 1, ac = (tid & 1) * 16;
    int row = bm + ar;
    const __nv_bfloat16* Ap = A + (size_t)row * lda + k0 + ac;
    bool ok = row < M;
    uint4 z = make_uint4(0, 0, 0, 0);
    uint4 r0 = ok ? *(const uint4*)Ap : z;
    uint4 r1 = ok ? *(const uint4*)(Ap + 8) : z;
    const __nv_bfloat162* p0 = (const __nv_bfloat162*)&r0;
    const __nv_bfloat162* p1 = (const __nv_bfloat162*)&r1;
#pragma unroll
    for (int j = 0; j < 4; j++) {
        float2 f0 = __bfloat1622float2(p0[j]);
        float2 f1 = __bfloat1622float2(p1[j]);
        As[ar][ac + 2 * j + 0] = f2tf(f0.x);
        As[ar][ac + 2 * j + 1] = f2tf(f0.y);
        As[ar][ac + 8 + 2 * j + 0] = f2tf(f1.x);
        As[ar][ac + 8 + 2 * j + 1] = f2tf(f1.y);
    }
}

// one 32-wide K chunk: 4 k-steps of m16n8k8 across warp's 32x32 tile
__device__ __forceinline__ void mma_stage(const unsigned (*As)[36], const uint2* __restrict__ bst,
                                          float acc[2][4][4], int wm, int wn, int g, int tg,
                                          int lane) {
#pragma unroll
    for (int s = 0; s < 4; s++) {
        unsigned a[2][4];
#pragma unroll
        for (int t = 0; t < 2; t++) {
            int r = wm * 32 + t * 16 + g;
            a[t][0] = As[r][s * 8 + tg];
            a[t][1] = As[r + 8][s * 8 + tg];
            a[t][2] = As[r][s * 8 + tg + 4];
            a[t][3] = As[r + 8][s * 8 + tg + 4];
        }
        const uint2* bp = bst + ((s * 2 + wn) * 4) * 32 + lane;
#pragma unroll
        for (int u = 0; u < 4; u++) {
            uint2 b = bp[u * 32];
#pragma unroll
            for (int t = 0; t < 2; t++)
                mma8(acc[t][u], a[t][0], a[t][1], a[t][2], a[t][3], b.x, b.y);
        }
    }
}

// ---------------- CSR build -------------------------------------------------
__global__ void zero_int_kernel(int* p, int n) {
    int i = blockIdx.x * blockDim.x + threadIdx.x;
    if (i < n) p[i] = 0;
}

__global__ void count_kernel(const int* __restrict__ edge_index, int* __restrict__ cnt) {
    int i = blockIdx.x * blockDim.x + threadIdx.x;
    if (i < Ee) atomicAdd(&cnt[edge_index[Ee + i]], 1);
}

__global__ void scan_partial_kernel(const int* __restrict__ cnt, int* __restrict__ partial) {
    __shared__ int sh[256];
    int b = blockIdx.x, tid = threadIdx.x;
    int base = b * SCAN_CHUNK;
    int s = 0;
#pragma unroll
    for (int j = 0; j < SCAN_CHUNK / 256; j++) {
        int i = base + j * 256 + tid;
        s += (i < Nn) ? cnt[i] : 0;
    }
    sh[tid] = s;
    __syncthreads();
    for (int st = 128; st >= 1; st >>= 1) {
        if (tid < st) sh[tid] += sh[tid + st];
        __syncthreads();
    }
    if (tid == 0) partial[b] = sh[0];
}

__global__ void scan_base_kernel(const int* __restrict__ partial, int* __restrict__ base,
                                 int* __restrict__ off) {
    if (threadIdx.x == 0) {
        int run = 0;
        for (int i = 0; i < SCAN_BLOCKS; i++) { base[i] = run; run += partial[i]; }
        off[Nn] = run;
    }
}

__global__ void scan_final_kernel(const int* __restrict__ cnt, const int* __restrict__ base,
                                  int* __restrict__ off, int* __restrict__ cur) {
    __shared__ int sh[SCAN_CHUNK];
    int b = blockIdx.x, tid = threadIdx.x;
    int i = b * SCAN_CHUNK + tid;
    int v = (i < Nn) ? cnt[i] : 0;
    sh[tid] = v;
    __syncthreads();
    for (int s = 1; s < SCAN_CHUNK; s <<= 1) {
        int t2 = (tid >= s) ? sh[tid - s] : 0;
        __syncthreads();
        sh[tid] += t2;
        __syncthreads();
    }
    if (i < Nn) {
        int excl = sh[tid] - v + base[b];
        off[i] = excl;
        cur[i] = excl;
    }
}

__global__ void scatter_kernel(const int* __restrict__ edge_index, int* __restrict__ cur,
                               int* __restrict__ srcs, int* __restrict__ eids) {
    int i = blockIdx.x * blockDim.x + threadIdx.x;
    if (i < Ee) {
        int src = edge_index[i];
        int dst = edge_index[Ee + i];
        int pos = atomicAdd(&cur[dst], 1);
        srcs[pos] = src;
        eids[pos] = i;
    }
}

// permute fp8 edge features into CSR order: e8p[i] = eb8[eids[i]] (16B chunks)
__global__ void reorder_e_kernel(const unsigned char* __restrict__ eb8,
                                 const int* __restrict__ eids,
                                 unsigned char* __restrict__ e8p) {
    int idx = blockIdx.x * blockDim.x + threadIdx.x;
    if (idx >= Ee * 4) return;
    int i = idx >> 2;
    int c = (idx & 3) * 16;
    int eid = eids[i];
    *(uint4*)(e8p + (size_t)i * 64 + c) = *(const uint4*)(eb8 + (size_t)eid * 64 + c);
}

// ---------------- weight packing (fused) -------------------------------------
__global__ void pack_stage1(const float* __restrict__ Wq, const float* __restrict__ bq,
                            const float* __restrict__ Wk, const float* __restrict__ bk,
                            const float* __restrict__ Wv, const float* __restrict__ bv,
                            const float* __restrict__ We, const float* __restrict__ Wskip,
                            float* __restrict__ Bp, float* __restrict__ biasp,
                            float* __restrict__ Bc) {
    int idx = blockIdx.x * blockDim.x + threadIdx.x;
    if (idx < LAYERS * 65536) {
        int l = idx >> 16;
        int rem = idx & 65535;
        int j = rem >> 10;
        int col = rem & 1023;
        const float* Wql = Wq + l * 16384;
        const float* Wkl = Wk + l * 16384;
        const float* Wvl = Wv + l * 16384;
        const float* Wel = We + l * 16384;
        float v;
        if (col < 256) v = Wql[j * 256 + col];
        else if (col < 512) v = Wkl[j * 256 + col - 256];
        else if (col < 768) v = Wvl[j * 256 + col - 512];
        else {
            int d2 = col - 768; int h = d2 >> 6; int d = d2 & 63;
            float s = 0.f;
            for (int c = 0; c < 64; c++)
                s += Wql[j * 256 + h * 64 + c] * Wel[d * 256 + h * 64 + c];
            v = s;
        }
        Bp[idx] = v;
        if (j == 0) {
            float bvv;
            if (col < 256) bvv = bq[l * 256 + col];
            else if (col < 512) bvv = bk[l * 256 + col - 256];
            else if (col < 768) bvv = bv[l * 256 + col - 512];
            else {
                int d2 = col - 768; int h = d2 >> 6; int d = d2 & 63;
                float s = 0.f;
                for (int c = 0; c < 64; c++)
                    s += bq[l * 256 + h * 64 + c] * Wel[d * 256 + h * 64 + c];
                bvv = s;
            }
            biasp[l * 1024 + col] = bvv;
        }
    } else {
        int j = idx - LAYERS * 65536;
        if (j >= LAYERS * 320 * 64) return;
        int l = j / (320 * 64);
        int r = (j >> 6) % 320;
        int c = j & 63;
        float v;
        if (r < 256) {
            int h = r >> 6, d = r & 63;
            v = We[l * 16384 + d * 256 + h * 64 + c];
        } else {
            v = Wskip[l * 4096 + (r - 256) * 64 + c];
        }
        Bc[j] = v;
    }
}

__device__ __forceinline__ void frag_pack(const float* __restrict__ B, unsigned* __restrict__ out,
                                          int idx, int K, int Ncols) {
    int ks_total = K >> 3;
    int p = idx & 1;
    int lane = (idx >> 1) & 31;
    int u = (idx >> 6) & 3;
    int wn = (idx >> 8) & 1;
    int rest = idx >> 9;
    int ks = rest % ks_total;
    int bnb = rest / ks_total;
    int k = ks * 8 + (lane & 3) + 4 * p;
    int n = bnb * 64 + wn * 32 + u * 8 + (lane >> 2);
    out[idx] = f2tf(B[k * Ncols + n]);
}

__global__ void pack_frag(const float* __restrict__ B, unsigned* __restrict__ out,
                          int K, int Ncols) {
    int idx = blockIdx.x * blockDim.x + threadIdx.x;
    if (idx < K * Ncols) frag_pack(B, out, idx, K, Ncols);
}

__global__ void pack_stage2(const float* __restrict__ Bp, const float* __restrict__ Bc,
                            unsigned* __restrict__ BfQ, unsigned* __restrict__ BfC) {
    int idx = blockIdx.x * blockDim.x + threadIdx.x;
    if (idx < LAYERS * 65536) {
        int l = idx >> 16;
        frag_pack(Bp + l * 65536, BfQ + l * 65536, idx & 65535, 64, 1024);
    } else {
        int j = idx - LAYERS * 65536;
        if (j >= LAYERS * 20480) return;
        int l = j / 20480;
        frag_pack(Bc + l * 20480, BfC + l * 20480, j % 20480, 320, 64);
    }
}

// ---------------- node projection (tf32 MMA, double-buffered) ---------------
__global__ void gemm_h_mma(const float* __restrict__ A, const unsigned* __restrict__ Bf,
                           const float* __restrict__ bias, float* __restrict__ C,
                           int M, int K, int lda) {
    __shared__ unsigned As[2][128][36];
    float acc[2][4][4] = {};
    int bm = blockIdx.x * 128;
    int tid = threadIdx.x, w = tid >> 5, lane = tid & 31;
    int wm = w & 3, wn = w >> 2, g = lane >> 2, tg = lane & 3;
    int nst = K >> 5;
    stage_A(A, lda, bm, M, 0, As[0], tid);
    __syncthreads();
    for (int st = 0; st < nst; st++) {
        int cb = st & 1;
        if (st + 1 < nst) stage_A(A, lda, bm, M, (st + 1) * 32, As[cb ^ 1], tid);
        mma_stage(As[cb], (const uint2*)Bf + st * 1024, acc, wm, wn, g, tg, lane);
        __syncthreads();
    }
#pragma unroll
    for (int u = 0; u < 4; u++) {
        int col = wn * 32 + u * 8 + 2 * tg;
        float2 bb = *(const float2*)(bias + col);
#pragma unroll
        for (int t = 0; t < 2; t++) {
            int row = bm + wm * 32 + t * 16 + g;
            if (row < M) {
                float2 o = {acc[t][u][0] + bb.x, acc[t][u][1] + bb.y};
                *(float2*)(C + (size_t)row * 64 + col) = o;
            }
            if (row + 8 < M) {
                float2 o = {acc[t][u][2] + bb.x, acc[t][u][3] + bb.y};
                *(float2*)(C + (size_t)(row + 8) * 64 + col) = o;
            }
        }
    }
}

// ---------------- fused QKVQE (tf32 MMA): A staged once per 4 n-blocks ------
// q/qe -> bf16 qq; k/v -> fp8 kv8. j-loop NOT unrolled (register reuse).
__global__ void __launch_bounds__(256)
gemm_qkvqe_mma(const float* __restrict__ h, const unsigned* __restrict__ BfQ,
               const float* __restrict__ biasp,
               __nv_bfloat16* __restrict__ qq, unsigned char* __restrict__ kv8) {
    __shared__ unsigned As[2][128][36];
    int bm = blockIdx.x * 128;
    int tid = threadIdx.x, w = tid >> 5, lane = tid & 31;
    int wm = w & 3, wn = w >> 2, g = lane >> 2, tg = lane & 3;
    stage_A(h, 64, bm, Nn, 0, As[0], tid);
    stage_A(h, 64, bm, Nn, 32, As[1], tid);
    __syncthreads();
#pragma unroll 1
    for (int j = 0; j < 4; j++) {
        int bn = blockIdx.y * 4 + j;
        const uint2* Bfb = (const uint2*)BfQ + bn * 2048;
        float acc[2][4][4] = {};
        mma_stage(As[0], Bfb, acc, wm, wn, g, tg, lane);
        mma_stage(As[1], Bfb + 1024, acc, wm, wn, g, tg, lane);
        int sec = bn >> 2;
#pragma unroll
        for (int u = 0; u < 4; u++) {
            int colL = wn * 32 + u * 8 + 2 * tg;
            float2 bb = *(const float2*)(biasp + bn * 64 + colL);
            int coff = (bn & 3) * 64 + colL;
#pragma unroll
            for (int t = 0; t < 2; t++) {
#pragma unroll
                for (int hh = 0; hh < 2; hh++) {
                    int row = bm + wm * 32 + t * 16 + g + 8 * hh;
                    if (row >= Nn) continue;
                    float v0 = acc[t][u][2 * hh + 0] + bb.x;
                    float v1 = acc[t][u][2 * hh + 1] + bb.y;
                    if (sec == 0 || sec == 3) {
                        __nv_bfloat16* dst = qq + (size_t)row * 512 + (sec == 3 ? 256 : 0) + coff;
                        *(__nv_bfloat162*)dst = __floats2bfloat162_rn(v0, v1);
                    } else {
                        unsigned char* dst = kv8 + (size_t)row * 512 + (sec == 2 ? 256 : 0) + coff;
                        *(unsigned short*)dst = f2_to_fp8x2(v0, v1);
                    }
                }
            }
        }
    }
}

// ---------------- fused conv (tf32 MMA, double-buffered) + LN + relu --------
__global__ void conv_ln_mma(const __nv_bfloat16* __restrict__ t, const float* __restrict__ hres,
                            const unsigned* __restrict__ BfC, const float* __restrict__ bskip,
                            const __nv_bfloat16* __restrict__ amean,
                            const float* __restrict__ gam,
                            const float* __restrict__ bet, float* __restrict__ hout) {
    __shared__ unsigned As[2][128][36];
    __shared__ float Ssum[128][2];
    __shared__ float Ssq[128][2];
    float acc[2][4][4] = {};
    int bm = blockIdx.x * 128;
    int tid = threadIdx.x, w = tid >> 5, lane = tid & 31;
    int wm = w & 3, wn = w >> 2, g = lane >> 2, tg = lane & 3;
    stage_Abf(t, 256, bm, Nn, 0, As[0], tid);
    __syncthreads();
    for (int st = 0; st < 10; st++) {
        int cb = st & 1;
        int nx = st + 1;
        if (nx < 8) stage_Abf(t, 256, bm, Nn, nx * 32, As[cb ^ 1], tid);
        else if (nx < 10) stage_A(hres, 64, bm, Nn, (nx - 8) * 32, As[cb ^ 1], tid);
        mma_stage(As[cb], (const uint2*)BfC + st * 1024, acc, wm, wn, g, tg, lane);
        __syncthreads();
    }
    float xs[2][4][4];
#pragma unroll
    for (int u = 0; u < 4; u++) {
        int col = wn * 32 + u * 8 + 2 * tg;
        float2 bb = *(const float2*)(bskip + col);
#pragma unroll
        for (int t2 = 0; t2 < 2; t2++) {
#pragma unroll
            for (int hh = 0; hh < 2; hh++) {
                int row = bm + wm * 32 + t2 * 16 + g + 8 * hh;
                float2 am = make_float2(0.f, 0.f), hr = make_float2(0.f, 0.f);
                if (row < Nn) {
                    am = __bfloat1622float2(
                        *(const __nv_bfloat162*)(amean + (size_t)row * 64 + col));
                    hr = *(const float2*)(hres + (size_t)row * 64 + col);
                }
                xs[t2][u][2 * hh + 0] = acc[t2][u][2 * hh + 0] + bb.x + am.x + hr.x;
                xs[t2][u][2 * hh + 1] = acc[t2][u][2 * hh + 1] + bb.y + am.y + hr.y;
            }
        }
    }
#pragma unroll
    for (int t2 = 0; t2 < 2; t2++) {
#pragma unroll
        for (int hh = 0; hh < 2; hh++) {
            float s = 0.f, q = 0.f;
#pragma unroll
            for (int u = 0; u < 4; u++) {
                float a = xs[t2][u][2 * hh + 0], b = xs[t2][u][2 * hh + 1];
                s += a + b;
                q += a * a + b * b;
            }
            s += __shfl_xor_sync(0xffffffffu, s, 1);
            s += __shfl_xor_sync(0xffffffffu, s, 2);
            q += __shfl_xor_sync(0xffffffffu, q, 1);
            q += __shfl_xor_sync(0xffffffffu, q, 2);
            if (tg == 0) {
                int lr = wm * 32 + t2 * 16 + g + 8 * hh;
                Ssum[lr][wn] = s;
                Ssq[lr][wn] = q;
            }
        }
    }
    __syncthreads();
#pragma unroll
    for (int t2 = 0; t2 < 2; t2++) {
#pragma unroll
        for (int hh = 0; hh < 2; hh++) {
            int lr = wm * 32 + t2 * 16 + g + 8 * hh;
            int row = bm + lr;
            float m = (Ssum[lr][0] + Ssum[lr][1]) * (1.f / 64.f);
            float var = (Ssq[lr][0] + Ssq[lr][1]) * (1.f / 64.f) - m * m;
            float rs = rsqrtf(var + 1e-5f);
            if (row >= Nn) continue;
#pragma unroll
            for (int u = 0; u < 4; u++) {
                int col = wn * 32 + u * 8 + 2 * tg;
                float2 gg = *(const float2*)(gam + col);
                float2 b2 = *(const float2*)(bet + col);
                float2 o;
                o.x = fmaxf((xs[t2][u][2 * hh + 0] - m) * rs * gg.x + b2.x, 0.f);
                o.y = fmaxf((xs[t2][u][2 * hh + 1] - m) * rs * gg.y + b2.y, 0.f);
                *(float2*)(hout + (size_t)row * 64 + col) = o;
            }
        }
    }
}

// ---------------- fused edge MLP (tf32 MMA): eb8 = fp8(relu(ea@W1+b1)@W2+b2)
__global__ void edge_mlp_mma(const float* __restrict__ ea, const float* __restrict__ W1,
                             const float* __restrict__ b1, const unsigned* __restrict__ BfE,
                             const float* __restrict__ b2, unsigned char* __restrict__ eb8) {
    __shared__ unsigned As[128][68];
    __shared__ float W1s[EDGE_DIM * HID];
    __shared__ float b1s[HID];
    int tid = threadIdx.x, w = tid >> 5, lane = tid & 31;
    int wm = w & 3, wn = w >> 2, g = lane >> 2, tg = lane & 3;
    int be = blockIdx.x * 128;
    for (int i = tid; i < EDGE_DIM * HID; i += 256) W1s[i] = W1[i];
    if (tid < HID) b1s[tid] = b1[tid];
    __syncthreads();
    {
        int r = tid >> 1, half = tid & 1;
        float av[EDGE_DIM];
        const float* eap = ea + (size_t)(be + r) * EDGE_DIM;
#pragma unroll
        for (int d = 0; d < EDGE_DIM; d++) av[d] = eap[d];
#pragma unroll
        for (int c = 0; c < 32; c++) {
            int col = half * 32 + c;
            float s = b1s[col];
#pragma unroll
            for (int d = 0; d < EDGE_DIM; d++) s += av[d] * W1s[d * HID + col];
            As[r][col] = f2tf(fmaxf(s, 0.f));
        }
    }
    __syncthreads();
    float acc[2][4][4] = {};
#pragma unroll
    for (int st = 0; st < 2; st++) {
#pragma unroll
        for (int s = 0; s < 4; s++) {
            unsigned a[2][4];
#pragma unroll
            for (int t = 0; t < 2; t++) {
                int r = wm * 32 + t * 16 + g;
                a[t][0] = As[r][st * 32 + s * 8 + tg];
                a[t][1] = As[r + 8][st * 32 + s * 8 + tg];
                a[t][2] = As[r][st * 32 + s * 8 + tg + 4];
                a[t][3] = As[r + 8][st * 32 + s * 8 + tg + 4];
            }
            const uint2* bp = (const uint2*)BfE + st * 1024 + ((s * 2 + wn) * 4) * 32 + lane;
#pragma unroll
            for (int u = 0; u < 4; u++) {
                uint2 b = bp[u * 32];
#pragma unroll
                for (int t = 0; t < 2; t++)
                    mma8(acc[t][u], a[t][0], a[t][1], a[t][2], a[t][3], b.x, b.y);
            }
        }
    }
#pragma unroll
    for (int u = 0; u < 4; u++) {
        int col = wn * 32 + u * 8 + 2 * tg;
        float2 bb = *(const float2*)(b2 + col);
#pragma unroll
        for (int t = 0; t < 2; t++) {
#pragma unroll
            for (int hh = 0; hh < 2; hh++) {
                int row = be + wm * 32 + t * 16 + g + 8 * hh;
                float v0 = acc[t][u][2 * hh + 0] + bb.x;
                float v1 = acc[t][u][2 * hh + 1] + bb.y;
                *(unsigned short*)(eb8 + (size_t)row * 64 + col) = f2_to_fp8x2(v0, v1);
            }
        }
    }
}

// ---------------- per-node attention: fp8 k/v/e gathers ----------------------
__device__ __forceinline__ float dotqk8(const float* qv, const float* qev, uint2 kr, uint2 er) {
    unsigned kw[2] = {kr.x, kr.y};
    unsigned ew[2] = {er.x, er.y};
    float p = 0.f;
#pragma unroll
    for (int w2 = 0; w2 < 2; w2++) {
#pragma unroll
        for (int hh = 0; hh < 2; hh++) {
            float2 kf = fp8x2_to_f2((unsigned short)((kw[w2] >> (16 * hh)) & 0xffffu));
            float2 ef = fp8x2_to_f2((unsigned short)((ew[w2] >> (16 * hh)) & 0xffffu));
            int o = w2 * 4 + hh * 2;
            p += qv[o] * kf.x + qv[o + 1] * kf.y;
            p += qev[o] * ef.x + qev[o + 1] * ef.y;
        }
    }
    return p;
}

__device__ __forceinline__ void aggr8(float* acc, float* tac, float wgt, uint2 vr, uint2 er) {
    unsigned vw[2] = {vr.x, vr.y};
    unsigned ew[2] = {er.x, er.y};
#pragma unroll
    for (int w2 = 0; w2 < 2; w2++) {
#pragma unroll
        for (int hh = 0; hh < 2; hh++) {
            float2 vf = fp8x2_to_f2((unsigned short)((vw[w2] >> (16 * hh)) & 0xffffu));
            float2 ef = fp8x2_to_f2((unsigned short)((ew[w2] >> (16 * hh)) & 0xffffu));
            int o = w2 * 4 + hh * 2;
            acc[o] += wgt * vf.x;
            acc[o + 1] += wgt * vf.y;
            tac[o] += wgt * ef.x;
            tac[o + 1] += wgt * ef.y;
        }
    }
}

__global__ void __launch_bounds__(256, 4)
attn_kernel(const __nv_bfloat16* __restrict__ qq,
            const unsigned char* __restrict__ kv8, const unsigned char* __restrict__ e8p,
            const int* __restrict__ off, const int* __restrict__ srcs,
            __nv_bfloat16* __restrict__ t_out, __nv_bfloat16* __restrict__ amean) {
    int warp = (blockIdx.x * blockDim.x + threadIdx.x) >> 5;
    if (warp >= Nn) return;
    int lane = threadIdx.x & 31;
    int g = lane >> 3;
    int li = lane & 7;
    int n = warp;
    int base = n * HC + g * 64 + li * 8;
    int hoff8 = g * 64 + li * 8;   // fp8: element offset == byte offset
    float qv[8], qev[8];
    {
        // bf16 q/qe load; fold softmax scale (1/8, exact pow2) into conversion
        uint4 qr = *(const uint4*)(qq + (size_t)n * 512 + hoff8);
        uint4 qer = *(const uint4*)(qq + (size_t)n * 512 + 256 + hoff8);
        const __nv_bfloat162* qp = (const __nv_bfloat162*)&qr;
        const __nv_bfloat162* qep = (const __nv_bfloat162*)&qer;
#pragma unroll
        for (int t = 0; t < 4; t++) {
            float2 f0 = __bfloat1622float2(qp[t]);
            float2 f1 = __bfloat1622float2(qep[t]);
            qv[2 * t] = f0.x * 0.125f; qv[2 * t + 1] = f0.y * 0.125f;
            qev[2 * t] = f1.x * 0.125f; qev[2 * t + 1] = f1.y * 0.125f;
        }
    }

    int s0 = off[n], s1 = off[n + 1];
    float denom = 0.f;
    float acc[8] = {}, tac[8] = {};

    int i = s0;
    for (; i + 2 <= s1; i += 2) {
        int n0 = srcs[i];
        int n1 = srcs[i + 1];
        uint2 k0 = *(const uint2*)(kv8 + (size_t)n0 * 512 + hoff8);
        uint2 k1 = *(const uint2*)(kv8 + (size_t)n1 * 512 + hoff8);
        uint2 v0 = *(const uint2*)(kv8 + (size_t)n0 * 512 + 256 + hoff8);
        uint2 v1 = *(const uint2*)(kv8 + (size_t)n1 * 512 + 256 + hoff8);
        uint2 e0 = *(const uint2*)(e8p + (size_t)i * 64 + li * 8);
        uint2 e1 = *(const uint2*)(e8p + (size_t)(i + 1) * 64 + li * 8);
        float p0 = dotqk8(qv, qev, k0, e0);
        float p1 = dotqk8(qv, qev, k1, e1);
        p0 += __shfl_xor_sync(0xffffffffu, p0, 1);
        p1 += __shfl_xor_sync(0xffffffffu, p1, 1);
        p0 += __shfl_xor_sync(0xffffffffu, p0, 2);
        p1 += __shfl_xor_sync(0xffffffffu, p1, 2);
        p0 += __shfl_xor_sync(0xffffffffu, p0, 4);
        p1 += __shfl_xor_sync(0xffffffffu, p1, 4);
        float w0 = __expf(p0);
        float w1 = __expf(p1);
        denom += w0 + w1;
        aggr8(acc, tac, w0, v0, e0);
        aggr8(acc, tac, w1, v1, e1);
    }
    if (i < s1) {
        int n0 = srcs[i];
        uint2 k0 = *(const uint2*)(kv8 + (size_t)n0 * 512 + hoff8);
        uint2 v0 = *(const uint2*)(kv8 + (size_t)n0 * 512 + 256 + hoff8);
        uint2 e0 = *(const uint2*)(e8p + (size_t)i * 64 + li * 8);
        float p0 = dotqk8(qv, qev, k0, e0);
        p0 += __shfl_xor_sync(0xffffffffu, p0, 1);
        p0 += __shfl_xor_sync(0xffffffffu, p0, 2);
        p0 += __shfl_xor_sync(0xffffffffu, p0, 4);
        float w0 = __expf(p0);
        denom += w0;
        aggr8(acc, tac, w0, v0, e0);
    }
    float inv = (denom > 0.f) ? 1.f / denom : 0.f;
    float qinv = 0.25f * inv;
    {
        uint4 to;
        __nv_bfloat162* top = (__nv_bfloat162*)&to;
#pragma unroll
        for (int t = 0; t < 4; t++)
            top[t] = __floats2bfloat162_rn(tac[2 * t] * qinv, tac[2 * t + 1] * qinv);
        *(uint4*)(t_out + base) = to;
    }
    float red[8];
#pragma unroll
    for (int j = 0; j < 8; j++) {
        float s = acc[j] * inv;
        s += __shfl_xor_sync(0xffffffffu, s, 8);
        s += __shfl_xor_sync(0xffffffffu, s, 16);
        red[j] = 0.25f * s;
    }
    if (g == 0) {
        uint4 ao;
        __nv_bfloat162* aop = (__nv_bfloat162*)&ao;
#pragma unroll
        for (int t = 0; t < 4; t++)
            aop[t] = __floats2bfloat162_rn(red[2 * t], red[2 * t + 1]);
        *(uint4*)(amean + (size_t)n * 64 + li * 8) = ao;
    }
}

// ---------------- mean-pool + classifier + log_softmax ----------------------
__global__ void pool_kernel(const float* __restrict__ h, const int* __restrict__ batch,
                            const float* __restrict__ clsW, const float* __restrict__ clsb,
                            float* __restrict__ out) {
    int gid = blockIdx.x;
    int c = threadIdx.x;
    int lo = 0, hi = Nn;
    while (lo < hi) { int mid = (lo + hi) >> 1; if (batch[mid] < gid) lo = mid + 1; else hi = mid; }
    int start = lo;
    lo = start; hi = Nn;
    while (lo < hi) { int mid = (lo + hi) >> 1; if (batch[mid] < gid + 1) lo = mid + 1; else hi = mid; }
    int end = lo;
    float acc = 0.f;
    for (int r = start; r < end; r++) acc += h[r * HID + c];
    int cntn = end - start;
    float pooled = acc / fmaxf((float)cntn, 1.f);
    __shared__ float ps[HID];
    __shared__ float lg[CLASSES];
    ps[c] = pooled;
    __syncthreads();
    if (c < CLASSES) {
        float s = clsb[c];
        for (int d = 0; d < HID; d++) s += ps[d] * clsW[d * CLASSES + c];
        lg[c] = s;
    }
    __syncthreads();
    if (c == 0) {
        float mm = fmaxf(lg[0], fmaxf(lg[1], lg[2]));
        float se = expf(lg[0] - mm) + expf(lg[1] - mm) + expf(lg[2] - mm);
        float lse = mm + logf(se);
        out[gid * CLASSES + 0] = lg[0] - lse;
        out[gid * CLASSES + 1] = lg[1] - lse;
        out[gid * CLASSES + 2] = lg[2] - lse;
    }
}

// ---------------- host launcher --------------------------------------------
extern "C" void kernel_launch(void* const* d_in, const int* in_sizes, int n_in,
                              void* d_out, int out_size) {
    (void)in_sizes; (void)n_in; (void)out_size;
    const float* x        = (const float*)d_in[0];
    const float* edgeattr = (const float*)d_in[1];
    const float* node_W   = (const float*)d_in[2];
    const float* node_b   = (const float*)d_in[3];
    const float* e1_W     = (const float*)d_in[4];
    const float* e1_b     = (const float*)d_in[5];
    const float* e2_W     = (const float*)d_in[6];
    const float* e2_b     = (const float*)d_in[7];
    const float* Wq       = (const float*)d_in[8];
    const float* bq       = (const float*)d_in[9];
    const float* Wk       = (const float*)d_in[10];
    const float* bk       = (const float*)d_in[11];
    const float* Wv       = (const float*)d_in[12];
    const float* bv       = (const float*)d_in[13];
    const float* We       = (const float*)d_in[14];
    const float* Wskip    = (const float*)d_in[15];
    const float* bskip    = (const float*)d_in[16];
    const float* ln_g     = (const float*)d_in[17];
    const float* ln_b     = (const float*)d_in[18];
    const float* cls_W    = (const float*)d_in[19];
    const float* cls_b    = (const float*)d_in[20];
    const int* edge_index = (const int*)d_in[21];
    const int* batch      = (const int*)d_in[22];
    float* out            = (float*)d_out;

    float *h0, *h1, *Bp, *biasp, *Bc;
    unsigned *BfQ, *BfC, *BfH, *BfE;
    __nv_bfloat16 *qq, *t, *amean;
    unsigned char *kv8, *eb8, *e8p;
    int *cnt, *off, *cur, *partial, *basep, *srcs, *eids;
    cudaGetSymbolAddress((void**)&h0, d_h0);
    cudaGetSymbolAddress((void**)&h1, d_h1);
    cudaGetSymbolAddress((void**)&qq, d_qq);
    cudaGetSymbolAddress((void**)&kv8, d_kv8);
    cudaGetSymbolAddress((void**)&eb8, d_eb8);
    cudaGetSymbolAddress((void**)&e8p, d_e8p);
    cudaGetSymbolAddress((void**)&t, d_t);
    cudaGetSymbolAddress((void**)&amean, d_amean);
    cudaGetSymbolAddress((void**)&Bp, d_Bp);
    cudaGetSymbolAddress((void**)&biasp, d_biasp);
    cudaGetSymbolAddress((void**)&Bc, d_Bc);
    cudaGetSymbolAddress((void**)&BfQ, d_BfQ);
    cudaGetSymbolAddress((void**)&BfC, d_BfC);
    cudaGetSymbolAddress((void**)&BfH, d_BfH);
    cudaGetSymbolAddress((void**)&BfE, d_BfE);
    cudaGetSymbolAddress((void**)&cnt, d_cnt);
    cudaGetSymbolAddress((void**)&off, d_off);
    cudaGetSymbolAddress((void**)&cur, d_cur);
    cudaGetSymbolAddress((void**)&partial, d_partial);
    cudaGetSymbolAddress((void**)&basep, d_base);
    cudaGetSymbolAddress((void**)&srcs, d_srcs);
    cudaGetSymbolAddress((void**)&eids, d_eids);

    // ---- multi-stream prologue: CSR (s3), packs (s1), gemm_h (s4), edge MLP (s2)
    cudaStream_t s1, s2, s3, s4;
    cudaStreamCreateWithFlags(&s1, cudaStreamNonBlocking);
    cudaStreamCreateWithFlags(&s2, cudaStreamNonBlocking);
    cudaStreamCreateWithFlags(&s3, cudaStreamNonBlocking);
    cudaStreamCreateWithFlags(&s4, cudaStreamNonBlocking);
    cudaEvent_t eFork, e1, e2, e3, e4;
    cudaEventCreateWithFlags(&eFork, cudaEventDisableTiming);
    cudaEventCreateWithFlags(&e1, cudaEventDisableTiming);
    cudaEventCreateWithFlags(&e2, cudaEventDisableTiming);
    cudaEventCreateWithFlags(&e3, cudaEventDisableTiming);
    cudaEventCreateWithFlags(&e4, cudaEventDisableTiming);

    cudaEventRecord(eFork, 0);
    cudaStreamWaitEvent(s1, eFork, 0);
    cudaStreamWaitEvent(s2, eFork, 0);
    cudaStreamWaitEvent(s3, eFork, 0);
    cudaStreamWaitEvent(s4, eFork, 0);

    // branch 3 (s3): CSR build
    zero_int_kernel<<<(Nn + 255) / 256, 256, 0, s3>>>(cnt, Nn);
    count_kernel<<<(Ee + 255) / 256, 256, 0, s3>>>(edge_index, cnt);
    scan_partial_kernel<<<SCAN_BLOCKS, 256, 0, s3>>>(cnt, partial);
    scan_base_kernel<<<1, 32, 0, s3>>>(partial, basep, off);
    scan_final_kernel<<<SCAN_BLOCKS, SCAN_CHUNK, 0, s3>>>(cnt, basep, off, cur);
    scatter_kernel<<<(Ee + 255) / 256, 256, 0, s3>>>(edge_index, cur, srcs, eids);
    cudaEventRecord(e3, s3);

    // branch 1 (s1): weight packs only
    {
        int n1 = LAYERS * 65536 + LAYERS * 320 * 64;
        pack_stage1<<<(n1 + 255) / 256, 256, 0, s1>>>(Wq, bq, Wk, bk, Wv, bv, We, Wskip,
                                                      Bp, biasp, Bc);
        int n2 = LAYERS * 65536 + LAYERS * 20480;
        pack_stage2<<<(n2 + 255) / 256, 256, 0, s1>>>(Bp, Bc, BfQ, BfC);
    }
    cudaEventRecord(e1, s1);

    // branch 4 (s4): node projection (independent of packs)
    pack_frag<<<(128 * 64 + 255) / 256, 256, 0, s4>>>(node_W, BfH, 128, 64);
    gemm_h_mma<<<(Nn + 127) / 128, 256, 0, s4>>>(x, BfH, node_b, h0, Nn, NODE_DIM, NODE_DIM);
    cudaEventRecord(e4, s4);

    // branch 2 (s2): edge MLP (fp8 out), then reorder into CSR order
    pack_frag<<<(64 * 64 + 255) / 256, 256, 0, s2>>>(e2_W, BfE, 64, 64);
    edge_mlp_mma<<<Ee / 128, 256, 0, s2>>>(edgeattr, e1_W, e1_b, BfE, e2_b, eb8);
    cudaStreamWaitEvent(s2, e3, 0);
    reorder_e_kernel<<<(Ee * 4 + 255) / 256, 256, 0, s2>>>(eb8, eids, e8p);
    cudaEventRecord(e2, s2);

    // stream 0: qkvqe l0 needs packs (s1) + h0 (s4)
    cudaStreamWaitEvent(0, e1, 0);
    cudaStreamWaitEvent(0, e4, 0);

    float* hc = h0;
    float* hn = h1;
    for (int l = 0; l < LAYERS; l++) {
        gemm_qkvqe_mma<<<dim3((Nn + 127) / 128, 4), 256>>>(hc, BfQ + l * 65536,
                                                           biasp + l * 1024, qq, kv8);
        if (l == 0) {  // attn additionally needs e8p (s2, which includes CSR)
            cudaStreamWaitEvent(0, e2, 0);
        }
        attn_kernel<<<(Nn * 32 + 255) / 256, 256>>>(qq, kv8, e8p, off, srcs, t, amean);
        conv_ln_mma<<<(Nn + 127) / 128, 256>>>(t, hc, BfC + l * 20480, bskip + l * 64,
                                               amean, ln_g + l * 64, ln_b + l * 64, hn);
        float* tmp = hc; hc = hn; hn = tmp;
    }
    pool_kernel<<<GRAPHS, HID>>>(hc, batch, cls_W, cls_b, out);

    cudaStreamDestroy(s1);
    cudaStreamDestroy(s2);
    cudaStreamDestroy(s3);
    cudaStreamDestroy(s4);
    cudaEventDestroy(eFork);
    cudaEventDestroy(e1);
    cudaEventDestroy(e2);
    cudaEventDestroy(e3);
    cudaEventDestroy(e4);
}